// round 10
// baseline (speedup 1.0000x reference)
#include <cuda_runtime.h>
#include <cuda_fp16.h>
#include <cstdint>

#define Bsz 2
#define Cc  256
#define Nn  4096
#define Hh  8
#define Gg  8
#define CPG 32
#define EPSv 1e-5f
// f16x2 constant: log2(e)/sqrt(32) ~= 0.255035  (f16 0x3415)
#define CEXPH2 0x34153415u

__device__ float   g_scale[Bsz * Cc];
__device__ float   g_shift[Bsz * Cc];
__device__ float   g_part[Bsz * Gg * 8 * 2];
__device__ __half  g_XNh[Bsz * Cc * Nn];
__device__ __half  g_Wh[4 * Cc * Cc];
__device__ __half  g_Qh[Bsz * Cc * Nn];
__device__ __half  g_Kh[Bsz * Cc * Nn];
__device__ __half  g_Vh[Bsz * Cc * Nn];
__device__ __half  g_AOh[Bsz * Cc * Nn];
__device__ __align__(16) uint8_t g_Qf8[Bsz * Hh * Nn * 32];
__device__ __align__(16) uint8_t g_Kf8[Bsz * Hh * Nn * 32];

// ---------------------------------------------------------------------------
// helpers
// ---------------------------------------------------------------------------
__device__ __forceinline__ uint32_t smem_u32(const void* p) {
    uint32_t a;
    asm("{ .reg .u64 t; cvta.to.shared.u64 t, %1; cvt.u32.u64 %0, t; }"
        : "=r"(a) : "l"(p));
    return a;
}
__device__ __forceinline__ void ldsm_x4(uint32_t r[4], uint32_t a) {
    asm volatile("ldmatrix.sync.aligned.m8n8.x4.shared.b16 {%0,%1,%2,%3}, [%4];"
                 : "=r"(r[0]), "=r"(r[1]), "=r"(r[2]), "=r"(r[3]) : "r"(a));
}
__device__ __forceinline__ void ldsm_x4t(uint32_t r[4], uint32_t a) {
    asm volatile("ldmatrix.sync.aligned.m8n8.x4.trans.shared.b16 {%0,%1,%2,%3}, [%4];"
                 : "=r"(r[0]), "=r"(r[1]), "=r"(r[2]), "=r"(r[3]) : "r"(a));
}
__device__ __forceinline__ void mma16816(float c[4], const uint32_t a[4],
                                         const uint32_t b0, const uint32_t b1) {
    asm volatile(
        "mma.sync.aligned.m16n8k16.row.col.f32.f16.f16.f32 "
        "{%0,%1,%2,%3}, {%4,%5,%6,%7}, {%8,%9}, {%0,%1,%2,%3};"
        : "+f"(c[0]), "+f"(c[1]), "+f"(c[2]), "+f"(c[3])
        : "r"(a[0]), "r"(a[1]), "r"(a[2]), "r"(a[3]), "r"(b0), "r"(b1));
}
__device__ __forceinline__ void mma_fp8(float c[4], const uint32_t a[4],
                                        const uint32_t b0, const uint32_t b1) {
    asm volatile(
        "mma.sync.aligned.m16n8k32.row.col.f32.e4m3.e4m3.f32 "
        "{%0,%1,%2,%3}, {%4,%5,%6,%7}, {%8,%9}, {%0,%1,%2,%3};"
        : "+f"(c[0]), "+f"(c[1]), "+f"(c[2]), "+f"(c[3])
        : "r"(a[0]), "r"(a[1]), "r"(a[2]), "r"(a[3]), "r"(b0), "r"(b1));
}
// pack two fp32 -> f16x2, scale by CEXP, exp2 both halves
__device__ __forceinline__ uint32_t exp2h2s(float lo, float hi) {
    uint32_t d;
    asm("{ .reg .b32 t;\n\t"
        "cvt.rn.f16x2.f32 t, %2, %1;\n\t"
        "mul.f16x2 t, t, %3;\n\t"
        "ex2.approx.f16x2 %0, t; }"
        : "=r"(d) : "f"(lo), "f"(hi), "r"(CEXPH2));
    return d;
}
__device__ __forceinline__ uint32_t packh2(float a, float b) {
    __half2 h = __floats2half2_rn(a, b);
    return *(uint32_t*)&h;
}
__device__ __forceinline__ void cp16(uint32_t dst, const void* src) {
    asm volatile("cp.async.cg.shared.global [%0], [%1], 16;"
                 :: "r"(dst), "l"(src) : "memory");
}
#define CP_COMMIT() asm volatile("cp.async.commit_group;" ::: "memory")
#define CP_WAIT2()  asm volatile("cp.async.wait_group 2;" ::: "memory")
#define CP_WAIT1()  asm volatile("cp.async.wait_group 1;" ::: "memory")
#define CP_WAIT0()  asm volatile("cp.async.wait_group 0;" ::: "memory")

// ---------------------------------------------------------------------------
// Kernel 1a: GroupNorm partial sums
// ---------------------------------------------------------------------------
__global__ void gn_part_kernel(const float* __restrict__ x) {
    int bg = blockIdx.x >> 3, slice = blockIdx.x & 7;
    int b = bg / Gg, g = bg % Gg;
    const float4* xp = (const float4*)(x + ((size_t)b * Cc + g * CPG) * Nn)
                     + slice * (CPG * Nn / 4 / 8);
    const int n4 = CPG * Nn / 4 / 8;

    float s = 0.f, ss = 0.f;
    for (int i = threadIdx.x; i < n4; i += 256) {
        float4 v = xp[i];
        s  += v.x + v.y + v.z + v.w;
        ss += v.x * v.x + v.y * v.y + v.z * v.z + v.w * v.w;
    }
    __shared__ float rs[8], rss[8];
    #pragma unroll
    for (int off = 16; off; off >>= 1) {
        s  += __shfl_down_sync(0xffffffffu, s, off);
        ss += __shfl_down_sync(0xffffffffu, ss, off);
    }
    int lane = threadIdx.x & 31, wid = threadIdx.x >> 5;
    if (lane == 0) { rs[wid] = s; rss[wid] = ss; }
    __syncthreads();
    if (threadIdx.x < 8) {
        s = rs[threadIdx.x]; ss = rss[threadIdx.x];
        #pragma unroll
        for (int off = 4; off; off >>= 1) {
            s  += __shfl_down_sync(0xffu, s, off);
            ss += __shfl_down_sync(0xffu, ss, off);
        }
        if (threadIdx.x == 0) {
            g_part[(bg * 8 + slice) * 2 + 0] = s;
            g_part[(bg * 8 + slice) * 2 + 1] = ss;
        }
    }
}

// ---------------------------------------------------------------------------
// Kernel 1b: finalize
// ---------------------------------------------------------------------------
__global__ void gn_fin_kernel(const float* __restrict__ w,
                              const float* __restrict__ bias) {
    int t = threadIdx.x;
    int c = t & 255;
    int bg = t >> 5;
    float s = 0.f, ss = 0.f;
    #pragma unroll
    for (int i = 0; i < 8; i++) {
        s  += g_part[(bg * 8 + i) * 2 + 0];
        ss += g_part[(bg * 8 + i) * 2 + 1];
    }
    const float inv = 1.f / (float)(CPG * Nn);
    float mu = s * inv;
    float var = ss * inv - mu * mu;
    float rstd = rsqrtf(var + EPSv);
    float sc = rstd * w[c];
    g_scale[t] = sc;
    g_shift[t] = bias[c] - mu * sc;
}

// ---------------------------------------------------------------------------
// Kernel 2: normalize -> fp16
// ---------------------------------------------------------------------------
__global__ void normalize_kernel(const float* __restrict__ x) {
    int base = blockIdx.x * 512 + threadIdx.x;
    #pragma unroll
    for (int u = 0; u < 2; u++) {
        int i = base + u * 256;
        int bc = i >> 10;
        float sc = g_scale[bc], sh = g_shift[bc];
        float4 v = ((const float4*)x)[i];
        uint2 o;
        o.x = packh2(fmaf(v.x, sc, sh), fmaf(v.y, sc, sh));
        o.y = packh2(fmaf(v.z, sc, sh), fmaf(v.w, sc, sh));
        ((uint2*)g_XNh)[i] = o;
    }
}

// ---------------------------------------------------------------------------
// Kernel 2b: weights -> fp16
// ---------------------------------------------------------------------------
__global__ void wconv_kernel(const float* __restrict__ w0, const float* __restrict__ w1,
                             const float* __restrict__ w2, const float* __restrict__ w3) {
    int i = blockIdx.x * blockDim.x + threadIdx.x;
    int sel = i >> 14;
    const float* w = (sel == 0) ? w0 : (sel == 1) ? w1 : (sel == 2) ? w2 : w3;
    float4 v = ((const float4*)w)[i & 16383];
    uint2 u;
    u.x = packh2(v.x, v.y);
    u.y = packh2(v.z, v.w);
    ((uint2*)g_Wh)[i] = u;
}

// ---------------------------------------------------------------------------
// Kernel 2c: transpose + convert Q/K fp16 [d][n] -> fp8 [n][d] per head.
// smem row stride 258 halves (516B, NOT 16B-aligned per row) -> fill must use
// 32-bit shared stores; only the gmem side uses 128-bit accesses.
// ---------------------------------------------------------------------------
__global__ void __launch_bounds__(256)
qkcvt_kernel(const __half* __restrict__ inp, uint8_t* __restrict__ outp) {
    __shared__ __half sm[32][258];
    int b = blockIdx.z, h = blockIdx.y, nt = blockIdx.x;
    const __half* in = inp + ((size_t)b * Cc + h * 32) * Nn + nt * 256;
    int tid = threadIdx.x;
    #pragma unroll
    for (int i = 0; i < 4; i++) {
        int idx = tid + i * 256;
        int row = idx >> 5, c8 = (idx & 31) << 3;
        uint4 v = *(const uint4*)(in + (size_t)row * Nn + c8);
        uint32_t a = smem_u32(&sm[row][c8]);   // 4B-aligned (516 % 4 == 0)
        asm volatile("st.shared.b32 [%0], %1;"      :: "r"(a),      "r"(v.x) : "memory");
        asm volatile("st.shared.b32 [%0+4], %1;"    :: "r"(a),      "r"(v.y) : "memory");
        asm volatile("st.shared.b32 [%0+8], %1;"    :: "r"(a),      "r"(v.z) : "memory");
        asm volatile("st.shared.b32 [%0+12], %1;"   :: "r"(a),      "r"(v.w) : "memory");
    }
    __syncthreads();
    uint8_t* out = outp + ((size_t)(b * Hh + h) * Nn + nt * 256 + tid) * 32;
    uint32_t o[8];
    #pragma unroll
    for (int k = 0; k < 8; k++) {
        float f0 = __half2float(sm[4 * k + 0][tid]);
        float f1 = __half2float(sm[4 * k + 1][tid]);
        float f2 = __half2float(sm[4 * k + 2][tid]);
        float f3 = __half2float(sm[4 * k + 3][tid]);
        uint16_t lo, hi;
        asm("cvt.rn.satfinite.e4m3x2.f32 %0, %1, %2;" : "=h"(lo) : "f"(f1), "f"(f0));
        asm("cvt.rn.satfinite.e4m3x2.f32 %0, %1, %2;" : "=h"(hi) : "f"(f3), "f"(f2));
        asm("mov.b32 %0, {%1, %2};" : "=r"(o[k]) : "h"(lo), "h"(hi));
    }
    *(uint4*)out = *(uint4*)&o[0];
    *(uint4*)(out + 16) = *(uint4*)&o[4];
}

// ---------------------------------------------------------------------------
// Kernel 3: stacked QKV GEMM (M=768). BM=64 BN=128 BK=32, 3-stage cp.async.
// ---------------------------------------------------------------------------
__global__ void __launch_bounds__(256)
gemm_qkv(const __half* __restrict__ Wp,
         const float* __restrict__ bq, const float* __restrict__ bk,
         const float* __restrict__ bv) {
    __shared__ __align__(16) __half sA[3][64][40];
    __shared__ __align__(16) __half sB[3][32][136];

    int bz = blockIdx.z;
    const __half* X = g_XNh + (size_t)bz * Cc * Nn;
    int n0 = blockIdx.x * 128;
    int mg = blockIdx.y * 64;
    int which = mg >> 8;
    int m0 = mg & 255;
    int tid = threadIdx.x, lane = tid & 31, wid = tid >> 5;
    int wm = wid & 1, wn = wid >> 1;
    int g = lane >> 2, tg = lane & 3;
    int r7 = lane & 7, sel = lane >> 3, r15 = lane & 15, hi8 = lane >> 4;

    float c[2][4][4] = {};

    auto issue = [&](int kt, int buf) {
        int k0 = kt * 32;
        int arow = tid >> 2, acc2 = (tid & 3) << 3;
        cp16(smem_u32(&sA[buf][arow][acc2]),
             Wp + (size_t)(mg + arow) * Cc + k0 + acc2);
        #pragma unroll
        for (int i = 0; i < 2; i++) {
            int idx = tid + i * 256;
            int brow = idx >> 4, bcc = (idx & 15) << 3;
            cp16(smem_u32(&sB[buf][brow][bcc]),
                 X + (size_t)(k0 + brow) * Nn + n0 + bcc);
        }
    };

    issue(0, 0); CP_COMMIT();
    issue(1, 1); CP_COMMIT();

    for (int kt = 0; kt < 8; kt++) {
        int cur = kt % 3;
        if (kt + 2 < 8)      { issue(kt + 2, (kt + 2) % 3); CP_COMMIT(); CP_WAIT2(); }
        else if (kt + 1 < 8) { CP_WAIT1(); }
        else                 { CP_WAIT0(); }
        __syncthreads();

        #pragma unroll
        for (int ks = 0; ks < 2; ks++) {
            uint32_t a[2][4], bf[2][4];
            #pragma unroll
            for (int mt = 0; mt < 2; mt++)
                ldsm_x4(a[mt],
                        smem_u32(&sA[cur][wm * 32 + mt * 16 + (sel & 1) * 8 + r7]
                                        [ks * 16 + (sel >> 1) * 8]));
            #pragma unroll
            for (int jp = 0; jp < 2; jp++)
                ldsm_x4t(bf[jp],
                         smem_u32(&sB[cur][ks * 16 + r15][wn * 32 + jp * 16 + hi8 * 8]));
            #pragma unroll
            for (int mt = 0; mt < 2; mt++)
                #pragma unroll
                for (int jp = 0; jp < 2; jp++) {
                    mma16816(c[mt][jp * 2 + 0], a[mt], bf[jp][0], bf[jp][1]);
                    mma16816(c[mt][jp * 2 + 1], a[mt], bf[jp][2], bf[jp][3]);
                }
        }
        __syncthreads();
    }

    __half* outp = ((which == 0) ? g_Qh : (which == 1) ? g_Kh : g_Vh)
                 + (size_t)bz * Cc * Nn;
    const float* bp = (which == 0) ? bq : (which == 1) ? bk : bv;
    #pragma unroll
    for (int mt = 0; mt < 2; mt++) {
        int m = m0 + wm * 32 + mt * 16 + g;
        float b0 = bp[m], b1 = bp[m + 8];
        #pragma unroll
        for (int jt = 0; jt < 4; jt++) {
            int n = n0 + wn * 32 + jt * 8 + 2 * tg;
            *(__half2*)(outp + (size_t)m * Nn + n) =
                __floats2half2_rn(c[mt][jt][0] + b0, c[mt][jt][1] + b0);
            *(__half2*)(outp + (size_t)(m + 8) * Nn + n) =
                __floats2half2_rn(c[mt][jt][2] + b1, c[mt][jt][3] + b1);
        }
    }
}

// ---------------------------------------------------------------------------
// Kernel 5: output projection GEMM + residual, fp32 out. 3-stage cp.async.
// ---------------------------------------------------------------------------
__global__ void __launch_bounds__(256)
gemm_o(const __half* __restrict__ Wp, const float* __restrict__ bias,
       const float* __restrict__ resid, float* __restrict__ Out) {
    __shared__ __align__(16) __half sA[3][64][40];
    __shared__ __align__(16) __half sB[3][32][136];

    int bz = blockIdx.z;
    const __half* X = g_AOh + (size_t)bz * Cc * Nn;
    int n0 = blockIdx.x * 128, m0 = blockIdx.y * 64;
    int tid = threadIdx.x, lane = tid & 31, wid = tid >> 5;
    int wm = wid & 1, wn = wid >> 1;
    int g = lane >> 2, tg = lane & 3;
    int r7 = lane & 7, sel = lane >> 3, r15 = lane & 15, hi8 = lane >> 4;

    float c[2][4][4] = {};

    auto issue = [&](int kt, int buf) {
        int k0 = kt * 32;
        int arow = tid >> 2, acc2 = (tid & 3) << 3;
        cp16(smem_u32(&sA[buf][arow][acc2]),
             Wp + (size_t)(m0 + arow) * Cc + k0 + acc2);
        #pragma unroll
        for (int i = 0; i < 2; i++) {
            int idx = tid + i * 256;
            int brow = idx >> 4, bcc = (idx & 15) << 3;
            cp16(smem_u32(&sB[buf][brow][bcc]),
                 X + (size_t)(k0 + brow) * Nn + n0 + bcc);
        }
    };

    issue(0, 0); CP_COMMIT();
    issue(1, 1); CP_COMMIT();

    for (int kt = 0; kt < 8; kt++) {
        int cur = kt % 3;
        if (kt + 2 < 8)      { issue(kt + 2, (kt + 2) % 3); CP_COMMIT(); CP_WAIT2(); }
        else if (kt + 1 < 8) { CP_WAIT1(); }
        else                 { CP_WAIT0(); }
        __syncthreads();

        #pragma unroll
        for (int ks = 0; ks < 2; ks++) {
            uint32_t a[2][4], bf[2][4];
            #pragma unroll
            for (int mt = 0; mt < 2; mt++)
                ldsm_x4(a[mt],
                        smem_u32(&sA[cur][wm * 32 + mt * 16 + (sel & 1) * 8 + r7]
                                        [ks * 16 + (sel >> 1) * 8]));
            #pragma unroll
            for (int jp = 0; jp < 2; jp++)
                ldsm_x4t(bf[jp],
                         smem_u32(&sB[cur][ks * 16 + r15][wn * 32 + jp * 16 + hi8 * 8]));
            #pragma unroll
            for (int mt = 0; mt < 2; mt++)
                #pragma unroll
                for (int jp = 0; jp < 2; jp++) {
                    mma16816(c[mt][jp * 2 + 0], a[mt], bf[jp][0], bf[jp][1]);
                    mma16816(c[mt][jp * 2 + 1], a[mt], bf[jp][2], bf[jp][3]);
                }
        }
        __syncthreads();
    }

    #pragma unroll
    for (int mt = 0; mt < 2; mt++) {
        int m = m0 + wm * 32 + mt * 16 + g;
        float b0 = bias[m], b1 = bias[m + 8];
        #pragma unroll
        for (int jt = 0; jt < 4; jt++) {
            int n = n0 + wn * 32 + jt * 8 + 2 * tg;
            size_t o0 = ((size_t)bz * Cc + m) * Nn + n;
            size_t o1 = ((size_t)bz * Cc + m + 8) * Nn + n;
            float2 r0 = *(const float2*)(resid + o0);
            float2 r1 = *(const float2*)(resid + o1);
            *(float2*)(Out + o0) = make_float2(c[mt][jt][0] + b0 + r0.x,
                                               c[mt][jt][1] + b0 + r0.y);
            *(float2*)(Out + o1) = make_float2(c[mt][jt][2] + b1 + r1.x,
                                               c[mt][jt][3] + b1 + r1.y);
        }
    }
}

// ---------------------------------------------------------------------------
// Kernel 4: flash attention, fp8 QK^T + fp16 PV.
// 256 threads (8 warps), 256 q/block, 2 blocks/SM, 3-stage cp.async.
// ---------------------------------------------------------------------------
__global__ void __launch_bounds__(256, 2)
attn_kernel() {
    __shared__ __align__(16) uint8_t sK8[3][64][48];
    __shared__ __align__(16) __half  sV[3][32][72];
    __shared__ __align__(16) __half  sO[32][264];

    int tid = threadIdx.x, lane = tid & 31, wid = tid >> 5;
    int b = blockIdx.z, h = blockIdx.y;
    int q0 = blockIdx.x * 256;
    size_t base = ((size_t)b * Cc + h * 32) * Nn;
    const __half* Vg = g_Vh + base;
    const uint8_t* Q8 = g_Qf8 + ((size_t)(b * Hh + h) * Nn + q0) * 32;
    const uint8_t* K8 = g_Kf8 + (size_t)(b * Hh + h) * Nn * 32;
    int g = lane >> 2, tg = lane & 3;
    int r7 = lane & 7, hi8 = lane >> 4;

    auto issue = [&](int t, int buf) {
        int row = tid >> 3, cc = (tid & 7) << 3;
        cp16(smem_u32(&sV[buf][row][cc]), Vg + (size_t)row * Nn + t * 64 + cc);
        if (tid < 128) {
            int kr = tid >> 1, kc = (tid & 1) << 4;
            cp16(smem_u32(&sK8[buf][kr][kc]), K8 + (size_t)(t * 64 + kr) * 32 + kc);
        }
    };

    issue(0, 0); CP_COMMIT();
    issue(1, 1); CP_COMMIT();

    // Q fp8 A-fragments (held whole kernel)
    uint32_t a8[2][4];
    #pragma unroll
    for (int mt = 0; mt < 2; mt++) {
        int qr = wid * 32 + mt * 16 + g;
        a8[mt][0] = *(const uint32_t*)(Q8 + (size_t)qr * 32 + 4 * tg);
        a8[mt][1] = *(const uint32_t*)(Q8 + (size_t)(qr + 8) * 32 + 4 * tg);
        a8[mt][2] = *(const uint32_t*)(Q8 + (size_t)qr * 32 + 16 + 4 * tg);
        a8[mt][3] = *(const uint32_t*)(Q8 + (size_t)(qr + 8) * 32 + 16 + 4 * tg);
    }

    float oc[2][4][4] = {};
    float rs[2][2] = {};

    for (int t = 0; t < Nn / 64; t++) {
        int cur = t % 3;
        if (t + 2 < Nn / 64)      { issue(t + 2, (t + 2) % 3); CP_COMMIT(); CP_WAIT2(); }
        else if (t + 1 < Nn / 64) { CP_WAIT1(); }
        else                      { CP_WAIT0(); }
        __syncthreads();

        #pragma unroll
        for (int jp = 0; jp < 4; jp++) {
            uint32_t pa[2][4];
            // S = Q K^T (fp8, K=32 in one MMA), P = exp2(scale*S)
            #pragma unroll
            for (int j2 = 0; j2 < 2; j2++) {
                int jb = jp * 2 + j2;
                const uint8_t* kr = &sK8[cur][jb * 8 + g][4 * tg];
                uint32_t b0 = *(const uint32_t*)kr;
                uint32_t b1 = *(const uint32_t*)(kr + 16);
                #pragma unroll
                for (int mt = 0; mt < 2; mt++) {
                    float sc[4] = {0.f, 0.f, 0.f, 0.f};
                    mma_fp8(sc, a8[mt], b0, b1);
                    pa[mt][j2 * 2 + 0] = exp2h2s(sc[0], sc[1]);
                    pa[mt][j2 * 2 + 1] = exp2h2s(sc[2], sc[3]);
                }
            }
            // row sums on fma pipe
            #pragma unroll
            for (int mt = 0; mt < 2; mt++) {
                __half2 s0 = __hadd2(*(__half2*)&pa[mt][0], *(__half2*)&pa[mt][2]);
                __half2 s1 = __hadd2(*(__half2*)&pa[mt][1], *(__half2*)&pa[mt][3]);
                float2 f0 = __half22float2(s0);
                float2 f1 = __half22float2(s1);
                rs[mt][0] += f0.x + f0.y;
                rs[mt][1] += f1.x + f1.y;
            }
            // O += P V^T (fp16)
            #pragma unroll
            for (int dnp = 0; dnp < 2; dnp++) {
                uint32_t vf[4];
                ldsm_x4(vf, smem_u32(&sV[cur][dnp * 16 + hi8 * 8 + r7]
                                            [jp * 16 + ((lane >> 3) & 1) * 8]));
                #pragma unroll
                for (int mt = 0; mt < 2; mt++) {
                    mma16816(oc[mt][dnp * 2],     pa[mt], vf[0], vf[1]);
                    mma16816(oc[mt][dnp * 2 + 1], pa[mt], vf[2], vf[3]);
                }
            }
        }
        __syncthreads();
    }

    // reduce row sums across the 4 tg lanes, normalize, stage O
    #pragma unroll
    for (int mt = 0; mt < 2; mt++) {
        #pragma unroll
        for (int r = 0; r < 2; r++) {
            rs[mt][r] += __shfl_xor_sync(0xffffffffu, rs[mt][r], 1);
            rs[mt][r] += __shfl_xor_sync(0xffffffffu, rs[mt][r], 2);
        }
        float inv0 = 1.f / rs[mt][0], inv1 = 1.f / rs[mt][1];
        int qc = wid * 32 + mt * 16;
        #pragma unroll
        for (int dn = 0; dn < 4; dn++) {
            int d0 = dn * 8 + 2 * tg;
            sO[d0][qc + g]         = __float2half(oc[mt][dn][0] * inv0);
            sO[d0 + 1][qc + g]     = __float2half(oc[mt][dn][1] * inv0);
            sO[d0][qc + g + 8]     = __float2half(oc[mt][dn][2] * inv1);
            sO[d0 + 1][qc + g + 8] = __float2half(oc[mt][dn][3] * inv1);
        }
    }
    __syncthreads();
    __half* AO = g_AOh + base;
    #pragma unroll
    for (int i = 0; i < 4; i++) {
        int idx = tid + i * 256;
        int row = idx >> 5, cc = (idx & 31) << 3;
        *(uint4*)(AO + (size_t)row * Nn + q0 + cc) = *(uint4*)&sO[row][cc];
    }
}

// ---------------------------------------------------------------------------
// Launch
// ---------------------------------------------------------------------------
extern "C" void kernel_launch(void* const* d_in, const int* in_sizes, int n_in,
                              void* d_out, int out_size) {
    const float* x    = (const float*)d_in[0];
    const float* gn_w = (const float*)d_in[1];
    const float* gn_b = (const float*)d_in[2];
    const float* wq   = (const float*)d_in[3];
    const float* bq   = (const float*)d_in[4];
    const float* wk   = (const float*)d_in[5];
    const float* bk   = (const float*)d_in[6];
    const float* wv   = (const float*)d_in[7];
    const float* bv   = (const float*)d_in[8];
    const float* wo   = (const float*)d_in[9];
    const float* bo   = (const float*)d_in[10];
    float* out = (float*)d_out;

    __half *wh, *qh, *kh;
    uint8_t *qf8, *kf8;
    cudaGetSymbolAddress((void**)&wh,  g_Wh);
    cudaGetSymbolAddress((void**)&qh,  g_Qh);
    cudaGetSymbolAddress((void**)&kh,  g_Kh);
    cudaGetSymbolAddress((void**)&qf8, g_Qf8);
    cudaGetSymbolAddress((void**)&kf8, g_Kf8);

    wconv_kernel<<<256, 256>>>(wq, wk, wv, wo);
    gn_part_kernel<<<128, 256>>>(x);
    gn_fin_kernel<<<1, 512>>>(gn_w, gn_b);
    normalize_kernel<<<(Bsz * Cc * Nn / 4) / 512, 256>>>(x);

    gemm_qkv<<<dim3(Nn / 128, 12, Bsz), 256>>>(wh, bq, bk, bv);

    dim3 cvg(Nn / 256, Hh, Bsz);
    qkcvt_kernel<<<cvg, 256>>>(qh, qf8);
    qkcvt_kernel<<<cvg, 256>>>(kh, kf8);

    attn_kernel<<<dim3(Nn / 256, Hh, Bsz), 256>>>();

    gemm_o<<<dim3(Nn / 128, Cc / 64, Bsz), 256>>>(wh + 3 * Cc * Cc, bo, x, out);
}

// round 11
// speedup vs baseline: 1.1242x; 1.1242x over previous
#include <cuda_runtime.h>
#include <cuda_fp16.h>
#include <cstdint>

#define Bsz 2
#define Cc  256
#define Nn  4096
#define Hh  8
#define Gg  8
#define CPG 32
#define EPSv 1e-5f
// log2(e)/sqrt(32)
#define CEXP 0.25503486f

__device__ float  g_scale[Bsz * Cc];
__device__ float  g_shift[Bsz * Cc];
__device__ float  g_part[Bsz * Gg * 8 * 2];
__device__ __half g_XNh[Bsz * Cc * Nn];
__device__ __half g_Wh[4 * Cc * Cc];
__device__ __half g_Qh[Bsz * Cc * Nn];
__device__ __half g_Kh[Bsz * Cc * Nn];
__device__ __half g_Vh[Bsz * Cc * Nn];
__device__ __half g_AOh[Bsz * Cc * Nn];

// ---------------------------------------------------------------------------
// helpers
// ---------------------------------------------------------------------------
__device__ __forceinline__ uint32_t smem_u32(const void* p) {
    uint32_t a;
    asm("{ .reg .u64 t; cvta.to.shared.u64 t, %1; cvt.u32.u64 %0, t; }"
        : "=r"(a) : "l"(p));
    return a;
}
__device__ __forceinline__ void ldsm_x4(uint32_t r[4], uint32_t a) {
    asm volatile("ldmatrix.sync.aligned.m8n8.x4.shared.b16 {%0,%1,%2,%3}, [%4];"
                 : "=r"(r[0]), "=r"(r[1]), "=r"(r[2]), "=r"(r[3]) : "r"(a));
}
__device__ __forceinline__ void ldsm_x4t(uint32_t r[4], uint32_t a) {
    asm volatile("ldmatrix.sync.aligned.m8n8.x4.trans.shared.b16 {%0,%1,%2,%3}, [%4];"
                 : "=r"(r[0]), "=r"(r[1]), "=r"(r[2]), "=r"(r[3]) : "r"(a));
}
__device__ __forceinline__ void mma16816(float c[4], const uint32_t a[4],
                                         const uint32_t b0, const uint32_t b1) {
    asm volatile(
        "mma.sync.aligned.m16n8k16.row.col.f32.f16.f16.f32 "
        "{%0,%1,%2,%3}, {%4,%5,%6,%7}, {%8,%9}, {%0,%1,%2,%3};"
        : "+f"(c[0]), "+f"(c[1]), "+f"(c[2]), "+f"(c[3])
        : "r"(a[0]), "r"(a[1]), "r"(a[2]), "r"(a[3]), "r"(b0), "r"(b1));
}
// pack two fp32 -> f16x2 (lo, hi), then exp2 both halves in one MUFU op
__device__ __forceinline__ uint32_t exp2h2(float lo, float hi) {
    uint32_t d;
    asm("{ .reg .b32 t;\n\t"
        "cvt.rn.f16x2.f32 t, %2, %1;\n\t"
        "ex2.approx.f16x2 %0, t; }"
        : "=r"(d) : "f"(lo), "f"(hi));
    return d;
}
__device__ __forceinline__ uint32_t packh2(float a, float b) {
    __half2 h = __floats2half2_rn(a, b);
    return *(uint32_t*)&h;
}
__device__ __forceinline__ void cp16(uint32_t dst, const void* src) {
    asm volatile("cp.async.cg.shared.global [%0], [%1], 16;"
                 :: "r"(dst), "l"(src) : "memory");
}
#define CP_COMMIT() asm volatile("cp.async.commit_group;" ::: "memory")
#define CP_WAIT2()  asm volatile("cp.async.wait_group 2;" ::: "memory")
#define CP_WAIT1()  asm volatile("cp.async.wait_group 1;" ::: "memory")
#define CP_WAIT0()  asm volatile("cp.async.wait_group 0;" ::: "memory")

// ---------------------------------------------------------------------------
// Kernel 1a: GroupNorm partial sums
// ---------------------------------------------------------------------------
__global__ void gn_part_kernel(const float* __restrict__ x) {
    int bg = blockIdx.x >> 3, slice = blockIdx.x & 7;
    int b = bg / Gg, g = bg % Gg;
    const float4* xp = (const float4*)(x + ((size_t)b * Cc + g * CPG) * Nn)
                     + slice * (CPG * Nn / 4 / 8);
    const int n4 = CPG * Nn / 4 / 8;

    float s = 0.f, ss = 0.f;
    for (int i = threadIdx.x; i < n4; i += 256) {
        float4 v = xp[i];
        s  += v.x + v.y + v.z + v.w;
        ss += v.x * v.x + v.y * v.y + v.z * v.z + v.w * v.w;
    }
    __shared__ float rs[8], rss[8];
    #pragma unroll
    for (int off = 16; off; off >>= 1) {
        s  += __shfl_down_sync(0xffffffffu, s, off);
        ss += __shfl_down_sync(0xffffffffu, ss, off);
    }
    int lane = threadIdx.x & 31, wid = threadIdx.x >> 5;
    if (lane == 0) { rs[wid] = s; rss[wid] = ss; }
    __syncthreads();
    if (threadIdx.x < 8) {
        s = rs[threadIdx.x]; ss = rss[threadIdx.x];
        #pragma unroll
        for (int off = 4; off; off >>= 1) {
            s  += __shfl_down_sync(0xffu, s, off);
            ss += __shfl_down_sync(0xffu, ss, off);
        }
        if (threadIdx.x == 0) {
            g_part[(bg * 8 + slice) * 2 + 0] = s;
            g_part[(bg * 8 + slice) * 2 + 1] = ss;
        }
    }
}

// ---------------------------------------------------------------------------
// Kernel 1b: finalize
// ---------------------------------------------------------------------------
__global__ void gn_fin_kernel(const float* __restrict__ w,
                              const float* __restrict__ bias) {
    int t = threadIdx.x;
    int c = t & 255;
    int bg = t >> 5;
    float s = 0.f, ss = 0.f;
    #pragma unroll
    for (int i = 0; i < 8; i++) {
        s  += g_part[(bg * 8 + i) * 2 + 0];
        ss += g_part[(bg * 8 + i) * 2 + 1];
    }
    const float inv = 1.f / (float)(CPG * Nn);
    float mu = s * inv;
    float var = ss * inv - mu * mu;
    float rstd = rsqrtf(var + EPSv);
    float sc = rstd * w[c];
    g_scale[t] = sc;
    g_shift[t] = bias[c] - mu * sc;
}

// ---------------------------------------------------------------------------
// Kernel 2: normalize -> fp16
// ---------------------------------------------------------------------------
__global__ void normalize_kernel(const float* __restrict__ x) {
    int base = blockIdx.x * 512 + threadIdx.x;
    #pragma unroll
    for (int u = 0; u < 2; u++) {
        int i = base + u * 256;
        int bc = i >> 10;
        float sc = g_scale[bc], sh = g_shift[bc];
        float4 v = ((const float4*)x)[i];
        uint2 o;
        o.x = packh2(fmaf(v.x, sc, sh), fmaf(v.y, sc, sh));
        o.y = packh2(fmaf(v.z, sc, sh), fmaf(v.w, sc, sh));
        ((uint2*)g_XNh)[i] = o;
    }
}

// ---------------------------------------------------------------------------
// Kernel 2b: weights -> fp16
// ---------------------------------------------------------------------------
__global__ void wconv_kernel(const float* __restrict__ w0, const float* __restrict__ w1,
                             const float* __restrict__ w2, const float* __restrict__ w3) {
    int i = blockIdx.x * blockDim.x + threadIdx.x;
    int sel = i >> 14;
    const float* w = (sel == 0) ? w0 : (sel == 1) ? w1 : (sel == 2) ? w2 : w3;
    float4 v = ((const float4*)w)[i & 16383];
    uint2 u;
    u.x = packh2(v.x, v.y);
    u.y = packh2(v.z, v.w);
    ((uint2*)g_Wh)[i] = u;
}

// ---------------------------------------------------------------------------
// Kernel 3: stacked QKV GEMM (M=768). BM=64 BN=128 BK=32, 3-stage cp.async.
// ---------------------------------------------------------------------------
__global__ void __launch_bounds__(256)
gemm_qkv(const __half* __restrict__ Wp,
         const float* __restrict__ bq, const float* __restrict__ bk,
         const float* __restrict__ bv) {
    __shared__ __align__(16) __half sA[3][64][40];
    __shared__ __align__(16) __half sB[3][32][136];

    int bz = blockIdx.z;
    const __half* X = g_XNh + (size_t)bz * Cc * Nn;
    int n0 = blockIdx.x * 128;
    int mg = blockIdx.y * 64;
    int which = mg >> 8;
    int m0 = mg & 255;
    int tid = threadIdx.x, lane = tid & 31, wid = tid >> 5;
    int wm = wid & 1, wn = wid >> 1;
    int g = lane >> 2, tg = lane & 3;
    int r7 = lane & 7, sel = lane >> 3, r15 = lane & 15, hi8 = lane >> 4;

    float c[2][4][4] = {};

    auto issue = [&](int kt, int buf) {
        int k0 = kt * 32;
        int arow = tid >> 2, acc2 = (tid & 3) << 3;
        cp16(smem_u32(&sA[buf][arow][acc2]),
             Wp + (size_t)(mg + arow) * Cc + k0 + acc2);
        #pragma unroll
        for (int i = 0; i < 2; i++) {
            int idx = tid + i * 256;
            int brow = idx >> 4, bcc = (idx & 15) << 3;
            cp16(smem_u32(&sB[buf][brow][bcc]),
                 X + (size_t)(k0 + brow) * Nn + n0 + bcc);
        }
    };

    issue(0, 0); CP_COMMIT();
    issue(1, 1); CP_COMMIT();

    for (int kt = 0; kt < 8; kt++) {
        int cur = kt % 3;
        if (kt + 2 < 8)      { issue(kt + 2, (kt + 2) % 3); CP_COMMIT(); CP_WAIT2(); }
        else if (kt + 1 < 8) { CP_WAIT1(); }
        else                 { CP_WAIT0(); }
        __syncthreads();

        #pragma unroll
        for (int ks = 0; ks < 2; ks++) {
            uint32_t a[2][4], bf[2][4];
            #pragma unroll
            for (int mt = 0; mt < 2; mt++)
                ldsm_x4(a[mt],
                        smem_u32(&sA[cur][wm * 32 + mt * 16 + (sel & 1) * 8 + r7]
                                        [ks * 16 + (sel >> 1) * 8]));
            #pragma unroll
            for (int jp = 0; jp < 2; jp++)
                ldsm_x4t(bf[jp],
                         smem_u32(&sB[cur][ks * 16 + r15][wn * 32 + jp * 16 + hi8 * 8]));
            #pragma unroll
            for (int mt = 0; mt < 2; mt++)
                #pragma unroll
                for (int jp = 0; jp < 2; jp++) {
                    mma16816(c[mt][jp * 2 + 0], a[mt], bf[jp][0], bf[jp][1]);
                    mma16816(c[mt][jp * 2 + 1], a[mt], bf[jp][2], bf[jp][3]);
                }
        }
        __syncthreads();
    }

    __half* outp = ((which == 0) ? g_Qh : (which == 1) ? g_Kh : g_Vh)
                 + (size_t)bz * Cc * Nn;
    const float* bp = (which == 0) ? bq : (which == 1) ? bk : bv;
    #pragma unroll
    for (int mt = 0; mt < 2; mt++) {
        int m = m0 + wm * 32 + mt * 16 + g;
        float b0 = bp[m], b1 = bp[m + 8];
        #pragma unroll
        for (int jt = 0; jt < 4; jt++) {
            int n = n0 + wn * 32 + jt * 8 + 2 * tg;
            *(__half2*)(outp + (size_t)m * Nn + n) =
                __floats2half2_rn(c[mt][jt][0] + b0, c[mt][jt][1] + b0);
            *(__half2*)(outp + (size_t)(m + 8) * Nn + n) =
                __floats2half2_rn(c[mt][jt][2] + b1, c[mt][jt][3] + b1);
        }
    }
}

// ---------------------------------------------------------------------------
// Kernel 5: output projection GEMM + residual, fp32 out. 3-stage cp.async.
// ---------------------------------------------------------------------------
__global__ void __launch_bounds__(256)
gemm_o(const __half* __restrict__ Wp, const float* __restrict__ bias,
       const float* __restrict__ resid, float* __restrict__ Out) {
    __shared__ __align__(16) __half sA[3][64][40];
    __shared__ __align__(16) __half sB[3][32][136];

    int bz = blockIdx.z;
    const __half* X = g_AOh + (size_t)bz * Cc * Nn;
    int n0 = blockIdx.x * 128, m0 = blockIdx.y * 64;
    int tid = threadIdx.x, lane = tid & 31, wid = tid >> 5;
    int wm = wid & 1, wn = wid >> 1;
    int g = lane >> 2, tg = lane & 3;
    int r7 = lane & 7, sel = lane >> 3, r15 = lane & 15, hi8 = lane >> 4;

    float c[2][4][4] = {};

    auto issue = [&](int kt, int buf) {
        int k0 = kt * 32;
        int arow = tid >> 2, acc2 = (tid & 3) << 3;
        cp16(smem_u32(&sA[buf][arow][acc2]),
             Wp + (size_t)(m0 + arow) * Cc + k0 + acc2);
        #pragma unroll
        for (int i = 0; i < 2; i++) {
            int idx = tid + i * 256;
            int brow = idx >> 4, bcc = (idx & 15) << 3;
            cp16(smem_u32(&sB[buf][brow][bcc]),
                 X + (size_t)(k0 + brow) * Nn + n0 + bcc);
        }
    };

    issue(0, 0); CP_COMMIT();
    issue(1, 1); CP_COMMIT();

    for (int kt = 0; kt < 8; kt++) {
        int cur = kt % 3;
        if (kt + 2 < 8)      { issue(kt + 2, (kt + 2) % 3); CP_COMMIT(); CP_WAIT2(); }
        else if (kt + 1 < 8) { CP_WAIT1(); }
        else                 { CP_WAIT0(); }
        __syncthreads();

        #pragma unroll
        for (int ks = 0; ks < 2; ks++) {
            uint32_t a[2][4], bf[2][4];
            #pragma unroll
            for (int mt = 0; mt < 2; mt++)
                ldsm_x4(a[mt],
                        smem_u32(&sA[cur][wm * 32 + mt * 16 + (sel & 1) * 8 + r7]
                                        [ks * 16 + (sel >> 1) * 8]));
            #pragma unroll
            for (int jp = 0; jp < 2; jp++)
                ldsm_x4t(bf[jp],
                         smem_u32(&sB[cur][ks * 16 + r15][wn * 32 + jp * 16 + hi8 * 8]));
            #pragma unroll
            for (int mt = 0; mt < 2; mt++)
                #pragma unroll
                for (int jp = 0; jp < 2; jp++) {
                    mma16816(c[mt][jp * 2 + 0], a[mt], bf[jp][0], bf[jp][1]);
                    mma16816(c[mt][jp * 2 + 1], a[mt], bf[jp][2], bf[jp][3]);
                }
        }
        __syncthreads();
    }

    #pragma unroll
    for (int mt = 0; mt < 2; mt++) {
        int m = m0 + wm * 32 + mt * 16 + g;
        float b0 = bias[m], b1 = bias[m + 8];
        #pragma unroll
        for (int jt = 0; jt < 4; jt++) {
            int n = n0 + wn * 32 + jt * 8 + 2 * tg;
            size_t o0 = ((size_t)bz * Cc + m) * Nn + n;
            size_t o1 = ((size_t)bz * Cc + m + 8) * Nn + n;
            float2 r0 = *(const float2*)(resid + o0);
            float2 r1 = *(const float2*)(resid + o1);
            *(float2*)(Out + o0) = make_float2(c[mt][jt][0] + b0 + r0.x,
                                               c[mt][jt][1] + b0 + r0.y);
            *(float2*)(Out + o1) = make_float2(c[mt][jt][2] + b1 + r1.x,
                                               c[mt][jt][3] + b1 + r1.y);
        }
    }
}

// ---------------------------------------------------------------------------
// Kernel 4: HMMA flash attention (fp16 QK + PV).
// 256 threads, 256 q/block, 2 blocks/SM, 3-stage cp.async.
// Scale folded into Q; P = ex2.approx.f16x2; row sums on the fma pipe
// (hadd2 + fp32 accumulate) so the tensor pipe runs only QK + PV (64 MMA/iter).
// ---------------------------------------------------------------------------
__global__ void __launch_bounds__(256, 2)
attn_kernel() {
    __shared__ __align__(16) __half sK[3][32][72];
    __shared__ __align__(16) __half sV[3][32][72];
    __shared__ __align__(16) __half sQ[32][264];   // Q staging, reused for O

    int tid = threadIdx.x, lane = tid & 31, wid = tid >> 5;
    int b = blockIdx.z, h = blockIdx.y;
    int q0 = blockIdx.x * 256;
    size_t base = ((size_t)b * Cc + h * 32) * Nn;
    const __half* Qg = g_Qh + base;
    const __half* Kg = g_Kh + base;
    const __half* Vg = g_Vh + base;
    int g = lane >> 2, tg = lane & 3;
    int r7 = lane & 7, sel = lane >> 3, r15 = lane & 15, hi8 = lane >> 4;

    auto issue = [&](int t, int buf) {
        int row = tid >> 3, cc = (tid & 7) << 3;
        size_t off = (size_t)row * Nn + t * 64 + cc;
        cp16(smem_u32(&sK[buf][row][cc]), Kg + off);
        cp16(smem_u32(&sV[buf][row][cc]), Vg + off);
    };

    issue(0, 0); CP_COMMIT();
    issue(1, 1); CP_COMMIT();

    // Q staging + fragments (scale folded in)
    #pragma unroll
    for (int i = 0; i < 4; i++) {
        int idx = tid + i * 256;
        int row = idx >> 5, cc = (idx & 31) << 3;
        *(uint4*)&sQ[row][cc] = *(const uint4*)(Qg + (size_t)row * Nn + q0 + cc);
    }
    __syncthreads();
    uint32_t qa[2][2][4];
    const __half2 cs2 = __float2half2_rn(CEXP);
    #pragma unroll
    for (int mt = 0; mt < 2; mt++)
        #pragma unroll
        for (int s = 0; s < 2; s++) {
            ldsm_x4t(qa[mt][s],
                     smem_u32(&sQ[s * 16 + (sel >> 1) * 8 + r7]
                                 [wid * 32 + mt * 16 + (sel & 1) * 8]));
            #pragma unroll
            for (int i = 0; i < 4; i++) {
                __half2 t2 = __hmul2(*(__half2*)&qa[mt][s][i], cs2);
                qa[mt][s][i] = *(uint32_t*)&t2;
            }
        }

    float oc[2][4][4] = {};
    float rs[2][2] = {};

    for (int t = 0; t < Nn / 64; t++) {
        int cur = t % 3;
        if (t + 2 < Nn / 64)      { issue(t + 2, (t + 2) % 3); CP_COMMIT(); CP_WAIT2(); }
        else if (t + 1 < Nn / 64) { CP_WAIT1(); }
        else                      { CP_WAIT0(); }
        __syncthreads();

        // per 16-key group: S -> P (exp2) -> fma-pipe rowsum -> PV
        #pragma unroll
        for (int jp = 0; jp < 4; jp++) {
            uint32_t kf[2][4];
            #pragma unroll
            for (int s = 0; s < 2; s++)
                ldsm_x4t(kf[s], smem_u32(&sK[cur][s * 16 + r15][jp * 16 + hi8 * 8]));
            uint32_t pa[2][4];
            #pragma unroll
            for (int mt = 0; mt < 2; mt++)
                #pragma unroll
                for (int j2 = 0; j2 < 2; j2++) {
                    float sc[4] = {0.f, 0.f, 0.f, 0.f};
                    mma16816(sc, qa[mt][0], kf[0][j2 * 2], kf[0][j2 * 2 + 1]);
                    mma16816(sc, qa[mt][1], kf[1][j2 * 2], kf[1][j2 * 2 + 1]);
                    pa[mt][j2 * 2 + 0] = exp2h2(sc[0], sc[1]);
                    pa[mt][j2 * 2 + 1] = exp2h2(sc[2], sc[3]);
                }
            // row sums on the fma pipe (regs 0,2 = row g; 1,3 = row g+8)
            #pragma unroll
            for (int mt = 0; mt < 2; mt++) {
                __half2 s0 = __hadd2(*(__half2*)&pa[mt][0], *(__half2*)&pa[mt][2]);
                __half2 s1 = __hadd2(*(__half2*)&pa[mt][1], *(__half2*)&pa[mt][3]);
                float2 f0 = __half22float2(s0);
                float2 f1 = __half22float2(s1);
                rs[mt][0] += f0.x + f0.y;
                rs[mt][1] += f1.x + f1.y;
            }
            // O += P V^T
            #pragma unroll
            for (int dnp = 0; dnp < 2; dnp++) {
                uint32_t vf[4];
                ldsm_x4(vf, smem_u32(&sV[cur][dnp * 16 + hi8 * 8 + r7]
                                            [jp * 16 + ((lane >> 3) & 1) * 8]));
                #pragma unroll
                for (int mt = 0; mt < 2; mt++) {
                    mma16816(oc[mt][dnp * 2],     pa[mt], vf[0], vf[1]);
                    mma16816(oc[mt][dnp * 2 + 1], pa[mt], vf[2], vf[3]);
                }
            }
        }
        __syncthreads();
    }

    // reduce row sums across the 4 tg lanes, normalize, stage O
    #pragma unroll
    for (int mt = 0; mt < 2; mt++) {
        #pragma unroll
        for (int r = 0; r < 2; r++) {
            rs[mt][r] += __shfl_xor_sync(0xffffffffu, rs[mt][r], 1);
            rs[mt][r] += __shfl_xor_sync(0xffffffffu, rs[mt][r], 2);
        }
        float inv0 = 1.f / rs[mt][0], inv1 = 1.f / rs[mt][1];
        int qc = wid * 32 + mt * 16;
        #pragma unroll
        for (int dn = 0; dn < 4; dn++) {
            int d0 = dn * 8 + 2 * tg;
            sQ[d0][qc + g]         = __float2half(oc[mt][dn][0] * inv0);
            sQ[d0 + 1][qc + g]     = __float2half(oc[mt][dn][1] * inv0);
            sQ[d0][qc + g + 8]     = __float2half(oc[mt][dn][2] * inv1);
            sQ[d0 + 1][qc + g + 8] = __float2half(oc[mt][dn][3] * inv1);
        }
    }
    __syncthreads();
    __half* AO = g_AOh + base;
    #pragma unroll
    for (int i = 0; i < 4; i++) {
        int idx = tid + i * 256;
        int row = idx >> 5, cc = (idx & 31) << 3;
        *(uint4*)(AO + (size_t)row * Nn + q0 + cc) = *(uint4*)&sQ[row][cc];
    }
}

// ---------------------------------------------------------------------------
// Launch
// ---------------------------------------------------------------------------
extern "C" void kernel_launch(void* const* d_in, const int* in_sizes, int n_in,
                              void* d_out, int out_size) {
    const float* x    = (const float*)d_in[0];
    const float* gn_w = (const float*)d_in[1];
    const float* gn_b = (const float*)d_in[2];
    const float* wq   = (const float*)d_in[3];
    const float* bq   = (const float*)d_in[4];
    const float* wk   = (const float*)d_in[5];
    const float* bk   = (const float*)d_in[6];
    const float* wv   = (const float*)d_in[7];
    const float* bv   = (const float*)d_in[8];
    const float* wo   = (const float*)d_in[9];
    const float* bo   = (const float*)d_in[10];
    float* out = (float*)d_out;

    __half* wh;
    cudaGetSymbolAddress((void**)&wh, g_Wh);

    wconv_kernel<<<256, 256>>>(wq, wk, wv, wo);
    gn_part_kernel<<<128, 256>>>(x);
    gn_fin_kernel<<<1, 512>>>(gn_w, gn_b);
    normalize_kernel<<<(Bsz * Cc * Nn / 4) / 512, 256>>>(x);

    gemm_qkv<<<dim3(Nn / 128, 12, Bsz), 256>>>(wh, bq, bk, bv);

    attn_kernel<<<dim3(Nn / 256, Hh, Bsz), 256>>>();

    gemm_o<<<dim3(Nn / 128, Cc / 64, Bsz), 256>>>(wh + 3 * Cc * Cc, bo, x, out);
}

// round 12
// speedup vs baseline: 1.1716x; 1.0422x over previous
#include <cuda_runtime.h>
#include <cuda_fp16.h>
#include <cstdint>

#define Bsz 2
#define Cc  256
#define Nn  4096
#define Hh  8
#define Gg  8
#define CPG 32
#define EPSv 1e-5f
// log2(e)/sqrt(32)
#define CEXP 0.25503486f

__device__ float  g_scale[Bsz * Cc];
__device__ float  g_shift[Bsz * Cc];
__device__ float  g_part[Bsz * Gg * 8 * 2];
__device__ __half g_XNh[Bsz * Cc * Nn];
__device__ __half g_Wh[4 * Cc * Cc];
__device__ __half g_Qh[Bsz * Cc * Nn];
__device__ __half g_Kh[Bsz * Cc * Nn];
__device__ __half g_Vh[Bsz * Cc * Nn];
__device__ __half g_AOh[Bsz * Cc * Nn];

// ---------------------------------------------------------------------------
// helpers
// ---------------------------------------------------------------------------
__device__ __forceinline__ uint32_t smem_u32(const void* p) {
    uint32_t a;
    asm("{ .reg .u64 t; cvta.to.shared.u64 t, %1; cvt.u32.u64 %0, t; }"
        : "=r"(a) : "l"(p));
    return a;
}
__device__ __forceinline__ void ldsm_x4(uint32_t r[4], uint32_t a) {
    asm volatile("ldmatrix.sync.aligned.m8n8.x4.shared.b16 {%0,%1,%2,%3}, [%4];"
                 : "=r"(r[0]), "=r"(r[1]), "=r"(r[2]), "=r"(r[3]) : "r"(a));
}
__device__ __forceinline__ void ldsm_x4t(uint32_t r[4], uint32_t a) {
    asm volatile("ldmatrix.sync.aligned.m8n8.x4.trans.shared.b16 {%0,%1,%2,%3}, [%4];"
                 : "=r"(r[0]), "=r"(r[1]), "=r"(r[2]), "=r"(r[3]) : "r"(a));
}
__device__ __forceinline__ void mma16816(float c[4], const uint32_t a[4],
                                         const uint32_t b0, const uint32_t b1) {
    asm volatile(
        "mma.sync.aligned.m16n8k16.row.col.f32.f16.f16.f32 "
        "{%0,%1,%2,%3}, {%4,%5,%6,%7}, {%8,%9}, {%0,%1,%2,%3};"
        : "+f"(c[0]), "+f"(c[1]), "+f"(c[2]), "+f"(c[3])
        : "r"(a[0]), "r"(a[1]), "r"(a[2]), "r"(a[3]), "r"(b0), "r"(b1));
}
// pack two fp32 -> f16x2 (lo, hi), then exp2 both halves in one MUFU op
__device__ __forceinline__ uint32_t exp2h2(float lo, float hi) {
    uint32_t d;
    asm("{ .reg .b32 t;\n\t"
        "cvt.rn.f16x2.f32 t, %2, %1;\n\t"
        "ex2.approx.f16x2 %0, t; }"
        : "=r"(d) : "f"(lo), "f"(hi));
    return d;
}
__device__ __forceinline__ uint32_t packh2(float a, float b) {
    __half2 h = __floats2half2_rn(a, b);
    return *(uint32_t*)&h;
}
__device__ __forceinline__ void cp16(uint32_t dst, const void* src) {
    asm volatile("cp.async.cg.shared.global [%0], [%1], 16;"
                 :: "r"(dst), "l"(src) : "memory");
}
#define CP_COMMIT() asm volatile("cp.async.commit_group;" ::: "memory")
#define CP_WAIT2()  asm volatile("cp.async.wait_group 2;" ::: "memory")
#define CP_WAIT1()  asm volatile("cp.async.wait_group 1;" ::: "memory")
#define CP_WAIT0()  asm volatile("cp.async.wait_group 0;" ::: "memory")

// ---------------------------------------------------------------------------
// Kernel 1a: GroupNorm partial sums
// ---------------------------------------------------------------------------
__global__ void gn_part_kernel(const float* __restrict__ x) {
    int bg = blockIdx.x >> 3, slice = blockIdx.x & 7;
    int b = bg / Gg, g = bg % Gg;
    const float4* xp = (const float4*)(x + ((size_t)b * Cc + g * CPG) * Nn)
                     + slice * (CPG * Nn / 4 / 8);
    const int n4 = CPG * Nn / 4 / 8;

    float s = 0.f, ss = 0.f;
    for (int i = threadIdx.x; i < n4; i += 256) {
        float4 v = xp[i];
        s  += v.x + v.y + v.z + v.w;
        ss += v.x * v.x + v.y * v.y + v.z * v.z + v.w * v.w;
    }
    __shared__ float rs[8], rss[8];
    #pragma unroll
    for (int off = 16; off; off >>= 1) {
        s  += __shfl_down_sync(0xffffffffu, s, off);
        ss += __shfl_down_sync(0xffffffffu, ss, off);
    }
    int lane = threadIdx.x & 31, wid = threadIdx.x >> 5;
    if (lane == 0) { rs[wid] = s; rss[wid] = ss; }
    __syncthreads();
    if (threadIdx.x < 8) {
        s = rs[threadIdx.x]; ss = rss[threadIdx.x];
        #pragma unroll
        for (int off = 4; off; off >>= 1) {
            s  += __shfl_down_sync(0xffu, s, off);
            ss += __shfl_down_sync(0xffu, ss, off);
        }
        if (threadIdx.x == 0) {
            g_part[(bg * 8 + slice) * 2 + 0] = s;
            g_part[(bg * 8 + slice) * 2 + 1] = ss;
        }
    }
}

// ---------------------------------------------------------------------------
// Kernel 1b: finalize
// ---------------------------------------------------------------------------
__global__ void gn_fin_kernel(const float* __restrict__ w,
                              const float* __restrict__ bias) {
    int t = threadIdx.x;
    int c = t & 255;
    int bg = t >> 5;
    float s = 0.f, ss = 0.f;
    #pragma unroll
    for (int i = 0; i < 8; i++) {
        s  += g_part[(bg * 8 + i) * 2 + 0];
        ss += g_part[(bg * 8 + i) * 2 + 1];
    }
    const float inv = 1.f / (float)(CPG * Nn);
    float mu = s * inv;
    float var = ss * inv - mu * mu;
    float rstd = rsqrtf(var + EPSv);
    float sc = rstd * w[c];
    g_scale[t] = sc;
    g_shift[t] = bias[c] - mu * sc;
}

// ---------------------------------------------------------------------------
// Kernel 2: normalize -> fp16
// ---------------------------------------------------------------------------
__global__ void normalize_kernel(const float* __restrict__ x) {
    int base = blockIdx.x * 512 + threadIdx.x;
    #pragma unroll
    for (int u = 0; u < 2; u++) {
        int i = base + u * 256;
        int bc = i >> 10;
        float sc = g_scale[bc], sh = g_shift[bc];
        float4 v = ((const float4*)x)[i];
        uint2 o;
        o.x = packh2(fmaf(v.x, sc, sh), fmaf(v.y, sc, sh));
        o.y = packh2(fmaf(v.z, sc, sh), fmaf(v.w, sc, sh));
        ((uint2*)g_XNh)[i] = o;
    }
}

// ---------------------------------------------------------------------------
// Kernel 2b: weights -> fp16
// ---------------------------------------------------------------------------
__global__ void wconv_kernel(const float* __restrict__ w0, const float* __restrict__ w1,
                             const float* __restrict__ w2, const float* __restrict__ w3) {
    int i = blockIdx.x * blockDim.x + threadIdx.x;
    int sel = i >> 14;
    const float* w = (sel == 0) ? w0 : (sel == 1) ? w1 : (sel == 2) ? w2 : w3;
    float4 v = ((const float4*)w)[i & 16383];
    uint2 u;
    u.x = packh2(v.x, v.y);
    u.y = packh2(v.z, v.w);
    ((uint2*)g_Wh)[i] = u;
}

// ---------------------------------------------------------------------------
// Kernel 3: stacked QKV GEMM (M=768). BM=128 BN=128 BK=32, 2-stage cp.async.
// 8 warps (2m x 4n), warp tile 64x32. Halves B-tile L2 traffic vs BM=64.
// ---------------------------------------------------------------------------
__global__ void __launch_bounds__(256)
gemm_qkv(const __half* __restrict__ Wp,
         const float* __restrict__ bq, const float* __restrict__ bk,
         const float* __restrict__ bv) {
    __shared__ __align__(16) __half sA[2][128][40];
    __shared__ __align__(16) __half sB[2][32][136];

    int bz = blockIdx.z;
    const __half* X = g_XNh + (size_t)bz * Cc * Nn;
    int n0 = blockIdx.x * 128;
    int mg = blockIdx.y * 128;           // global row in stacked [768, 256]
    int which = mg >> 8;                 // 0=Q 1=K 2=V
    int m0 = mg & 255;
    int tid = threadIdx.x, lane = tid & 31, wid = tid >> 5;
    int wm = wid & 1, wn = wid >> 1;
    int g = lane >> 2, tg = lane & 3;
    int r7 = lane & 7, sel = lane >> 3, r15 = lane & 15, hi8 = lane >> 4;

    float c[4][4][4] = {};

    auto issue = [&](int kt, int buf) {
        int k0 = kt * 32;
        #pragma unroll
        for (int i = 0; i < 2; i++) {
            int idx = tid + i * 256;
            int arow = idx >> 2, acol = (idx & 3) << 3;
            cp16(smem_u32(&sA[buf][arow][acol]),
                 Wp + (size_t)(mg + arow) * Cc + k0 + acol);
            int brow = idx >> 4, bcc = (idx & 15) << 3;
            cp16(smem_u32(&sB[buf][brow & 31][bcc]),
                 X + (size_t)(k0 + (brow & 31)) * Nn + n0 + bcc);
        }
    };
    // note: B rows 0..31 covered by idx 0..511 -> brow 0..31 with i=0 only;
    // for i=1 brow&31 repeats rows (harmless duplicate cp of same data).

    issue(0, 0); CP_COMMIT();

    for (int kt = 0; kt < 8; kt++) {
        int cur = kt & 1;
        if (kt + 1 < 8) { issue(kt + 1, cur ^ 1); CP_COMMIT(); CP_WAIT1(); }
        else            { CP_WAIT0(); }
        __syncthreads();

        #pragma unroll
        for (int ks = 0; ks < 2; ks++) {
            uint32_t a[4][4], bf[2][4];
            #pragma unroll
            for (int mt = 0; mt < 4; mt++)
                ldsm_x4(a[mt],
                        smem_u32(&sA[cur][wm * 64 + mt * 16 + (sel & 1) * 8 + r7]
                                        [ks * 16 + (sel >> 1) * 8]));
            #pragma unroll
            for (int jp = 0; jp < 2; jp++)
                ldsm_x4t(bf[jp],
                         smem_u32(&sB[cur][ks * 16 + r15][wn * 32 + jp * 16 + hi8 * 8]));
            #pragma unroll
            for (int mt = 0; mt < 4; mt++)
                #pragma unroll
                for (int jp = 0; jp < 2; jp++) {
                    mma16816(c[mt][jp * 2 + 0], a[mt], bf[jp][0], bf[jp][1]);
                    mma16816(c[mt][jp * 2 + 1], a[mt], bf[jp][2], bf[jp][3]);
                }
        }
        __syncthreads();
    }

    __half* outp = ((which == 0) ? g_Qh : (which == 1) ? g_Kh : g_Vh)
                 + (size_t)bz * Cc * Nn;
    const float* bp = (which == 0) ? bq : (which == 1) ? bk : bv;
    #pragma unroll
    for (int mt = 0; mt < 4; mt++) {
        int m = m0 + wm * 64 + mt * 16 + g;
        float b0 = bp[m], b1 = bp[m + 8];
        #pragma unroll
        for (int jt = 0; jt < 4; jt++) {
            int n = n0 + wn * 32 + jt * 8 + 2 * tg;
            *(__half2*)(outp + (size_t)m * Nn + n) =
                __floats2half2_rn(c[mt][jt][0] + b0, c[mt][jt][1] + b0);
            *(__half2*)(outp + (size_t)(m + 8) * Nn + n) =
                __floats2half2_rn(c[mt][jt][2] + b1, c[mt][jt][3] + b1);
        }
    }
}

// ---------------------------------------------------------------------------
// Kernel 5: output projection GEMM + residual, fp32 out.
// BM=128 BN=128 BK=32, 2-stage cp.async.
// ---------------------------------------------------------------------------
__global__ void __launch_bounds__(256)
gemm_o(const __half* __restrict__ Wp, const float* __restrict__ bias,
       const float* __restrict__ resid, float* __restrict__ Out) {
    __shared__ __align__(16) __half sA[2][128][40];
    __shared__ __align__(16) __half sB[2][32][136];

    int bz = blockIdx.z;
    const __half* X = g_AOh + (size_t)bz * Cc * Nn;
    int n0 = blockIdx.x * 128, m0 = blockIdx.y * 128;
    int tid = threadIdx.x, lane = tid & 31, wid = tid >> 5;
    int wm = wid & 1, wn = wid >> 1;
    int g = lane >> 2, tg = lane & 3;
    int r7 = lane & 7, sel = lane >> 3, r15 = lane & 15, hi8 = lane >> 4;

    float c[4][4][4] = {};

    auto issue = [&](int kt, int buf) {
        int k0 = kt * 32;
        #pragma unroll
        for (int i = 0; i < 2; i++) {
            int idx = tid + i * 256;
            int arow = idx >> 2, acol = (idx & 3) << 3;
            cp16(smem_u32(&sA[buf][arow][acol]),
                 Wp + (size_t)(m0 + arow) * Cc + k0 + acol);
            int brow = idx >> 4, bcc = (idx & 15) << 3;
            cp16(smem_u32(&sB[buf][brow & 31][bcc]),
                 X + (size_t)(k0 + (brow & 31)) * Nn + n0 + bcc);
        }
    };

    issue(0, 0); CP_COMMIT();

    for (int kt = 0; kt < 8; kt++) {
        int cur = kt & 1;
        if (kt + 1 < 8) { issue(kt + 1, cur ^ 1); CP_COMMIT(); CP_WAIT1(); }
        else            { CP_WAIT0(); }
        __syncthreads();

        #pragma unroll
        for (int ks = 0; ks < 2; ks++) {
            uint32_t a[4][4], bf[2][4];
            #pragma unroll
            for (int mt = 0; mt < 4; mt++)
                ldsm_x4(a[mt],
                        smem_u32(&sA[cur][wm * 64 + mt * 16 + (sel & 1) * 8 + r7]
                                        [ks * 16 + (sel >> 1) * 8]));
            #pragma unroll
            for (int jp = 0; jp < 2; jp++)
                ldsm_x4t(bf[jp],
                         smem_u32(&sB[cur][ks * 16 + r15][wn * 32 + jp * 16 + hi8 * 8]));
            #pragma unroll
            for (int mt = 0; mt < 4; mt++)
                #pragma unroll
                for (int jp = 0; jp < 2; jp++) {
                    mma16816(c[mt][jp * 2 + 0], a[mt], bf[jp][0], bf[jp][1]);
                    mma16816(c[mt][jp * 2 + 1], a[mt], bf[jp][2], bf[jp][3]);
                }
        }
        __syncthreads();
    }

    #pragma unroll
    for (int mt = 0; mt < 4; mt++) {
        int m = m0 + wm * 64 + mt * 16 + g;
        float b0 = bias[m], b1 = bias[m + 8];
        #pragma unroll
        for (int jt = 0; jt < 4; jt++) {
            int n = n0 + wn * 32 + jt * 8 + 2 * tg;
            size_t o0 = ((size_t)bz * Cc + m) * Nn + n;
            size_t o1 = ((size_t)bz * Cc + m + 8) * Nn + n;
            float2 r0 = *(const float2*)(resid + o0);
            float2 r1 = *(const float2*)(resid + o1);
            *(float2*)(Out + o0) = make_float2(c[mt][jt][0] + b0 + r0.x,
                                               c[mt][jt][1] + b0 + r0.y);
            *(float2*)(Out + o1) = make_float2(c[mt][jt][2] + b1 + r1.x,
                                               c[mt][jt][3] + b1 + r1.y);
        }
    }
}

// ---------------------------------------------------------------------------
// Kernel 4: HMMA flash attention (exact R7 structure — proven best).
// 256 threads, 256 q/block, 2 blocks/SM, 3-stage cp.async.
// Per 16-key group: QK-MMA -> exp -> rowsum-MMA(ones) -> PV-MMA.
// ---------------------------------------------------------------------------
__global__ void __launch_bounds__(256, 2)
attn_kernel() {
    __shared__ __align__(16) __half sK[3][32][72];
    __shared__ __align__(16) __half sV[3][32][72];
    __shared__ __align__(16) __half sQ[32][264];   // Q staging, reused for O

    int tid = threadIdx.x, lane = tid & 31, wid = tid >> 5;
    int b = blockIdx.z, h = blockIdx.y;
    int q0 = blockIdx.x * 256;
    size_t base = ((size_t)b * Cc + h * 32) * Nn;
    const __half* Qg = g_Qh + base;
    const __half* Kg = g_Kh + base;
    const __half* Vg = g_Vh + base;
    int g = lane >> 2, tg = lane & 3;
    int r7 = lane & 7, sel = lane >> 3, r15 = lane & 15, hi8 = lane >> 4;

    auto issue = [&](int t, int buf) {
        int row = tid >> 3, cc = (tid & 7) << 3;
        size_t off = (size_t)row * Nn + t * 64 + cc;
        cp16(smem_u32(&sK[buf][row][cc]), Kg + off);
        cp16(smem_u32(&sV[buf][row][cc]), Vg + off);
    };

    issue(0, 0); CP_COMMIT();
    issue(1, 1); CP_COMMIT();

    #pragma unroll
    for (int i = 0; i < 4; i++) {
        int idx = tid + i * 256;
        int row = idx >> 5, cc = (idx & 31) << 3;
        *(uint4*)&sQ[row][cc] = *(const uint4*)(Qg + (size_t)row * Nn + q0 + cc);
    }
    __syncthreads();
    uint32_t qa[2][2][4];
    const __half2 cs2 = __float2half2_rn(CEXP);
    #pragma unroll
    for (int mt = 0; mt < 2; mt++)
        #pragma unroll
        for (int s = 0; s < 2; s++) {
            ldsm_x4t(qa[mt][s],
                     smem_u32(&sQ[s * 16 + (sel >> 1) * 8 + r7]
                                 [wid * 32 + mt * 16 + (sel & 1) * 8]));
            #pragma unroll
            for (int i = 0; i < 4; i++) {
                __half2 t2 = __hmul2(*(__half2*)&qa[mt][s][i], cs2);
                qa[mt][s][i] = *(uint32_t*)&t2;
            }
        }

    float oc[2][4][4] = {};
    float rc[2][4] = {};
    const uint32_t ONES = 0x3C003C00u;

    for (int t = 0; t < Nn / 64; t++) {
        int cur = t % 3;
        if (t + 2 < Nn / 64)      { issue(t + 2, (t + 2) % 3); CP_COMMIT(); CP_WAIT2(); }
        else if (t + 1 < Nn / 64) { CP_WAIT1(); }
        else                      { CP_WAIT0(); }
        __syncthreads();

        #pragma unroll
        for (int jp = 0; jp < 4; jp++) {
            uint32_t kf[2][4];
            #pragma unroll
            for (int s = 0; s < 2; s++)
                ldsm_x4t(kf[s], smem_u32(&sK[cur][s * 16 + r15][jp * 16 + hi8 * 8]));
            uint32_t pa[2][4];
            #pragma unroll
            for (int mt = 0; mt < 2; mt++)
                #pragma unroll
                for (int j2 = 0; j2 < 2; j2++) {
                    float sc[4] = {0.f, 0.f, 0.f, 0.f};
                    mma16816(sc, qa[mt][0], kf[0][j2 * 2], kf[0][j2 * 2 + 1]);
                    mma16816(sc, qa[mt][1], kf[1][j2 * 2], kf[1][j2 * 2 + 1]);
                    pa[mt][j2 * 2 + 0] = exp2h2(sc[0], sc[1]);
                    pa[mt][j2 * 2 + 1] = exp2h2(sc[2], sc[3]);
                }
            #pragma unroll
            for (int mt = 0; mt < 2; mt++)
                mma16816(rc[mt], pa[mt], ONES, ONES);
            #pragma unroll
            for (int dnp = 0; dnp < 2; dnp++) {
                uint32_t vf[4];
                ldsm_x4(vf, smem_u32(&sV[cur][dnp * 16 + hi8 * 8 + r7]
                                            [jp * 16 + ((lane >> 3) & 1) * 8]));
                #pragma unroll
                for (int mt = 0; mt < 2; mt++) {
                    mma16816(oc[mt][dnp * 2],     pa[mt], vf[0], vf[1]);
                    mma16816(oc[mt][dnp * 2 + 1], pa[mt], vf[2], vf[3]);
                }
            }
        }
        __syncthreads();
    }

    #pragma unroll
    for (int mt = 0; mt < 2; mt++) {
        float inv0 = 1.f / rc[mt][0], inv1 = 1.f / rc[mt][2];
        int qc = wid * 32 + mt * 16;
        #pragma unroll
        for (int dn = 0; dn < 4; dn++) {
            int d0 = dn * 8 + 2 * tg;
            sQ[d0][qc + g]         = __float2half(oc[mt][dn][0] * inv0);
            sQ[d0 + 1][qc + g]     = __float2half(oc[mt][dn][1] * inv0);
            sQ[d0][qc + g + 8]     = __float2half(oc[mt][dn][2] * inv1);
            sQ[d0 + 1][qc + g + 8] = __float2half(oc[mt][dn][3] * inv1);
        }
    }
    __syncthreads();
    __half* AO = g_AOh + base;
    #pragma unroll
    for (int i = 0; i < 4; i++) {
        int idx = tid + i * 256;
        int row = idx >> 5, cc = (idx & 31) << 3;
        *(uint4*)(AO + (size_t)row * Nn + q0 + cc) = *(uint4*)&sQ[row][cc];
    }
}

// ---------------------------------------------------------------------------
// Launch
// ---------------------------------------------------------------------------
extern "C" void kernel_launch(void* const* d_in, const int* in_sizes, int n_in,
                              void* d_out, int out_size) {
    const float* x    = (const float*)d_in[0];
    const float* gn_w = (const float*)d_in[1];
    const float* gn_b = (const float*)d_in[2];
    const float* wq   = (const float*)d_in[3];
    const float* bq   = (const float*)d_in[4];
    const float* wk   = (const float*)d_in[5];
    const float* bk   = (const float*)d_in[6];
    const float* wv   = (const float*)d_in[7];
    const float* bv   = (const float*)d_in[8];
    const float* wo   = (const float*)d_in[9];
    const float* bo   = (const float*)d_in[10];
    float* out = (float*)d_out;

    __half* wh;
    cudaGetSymbolAddress((void**)&wh, g_Wh);

    wconv_kernel<<<256, 256>>>(wq, wk, wv, wo);
    gn_part_kernel<<<128, 256>>>(x);
    gn_fin_kernel<<<1, 512>>>(gn_w, gn_b);
    normalize_kernel<<<(Bsz * Cc * Nn / 4) / 512, 256>>>(x);

    gemm_qkv<<<dim3(Nn / 128, 6, Bsz), 256>>>(wh, bq, bk, bv);

    attn_kernel<<<dim3(Nn / 256, Hh, Bsz), 256>>>();

    gemm_o<<<dim3(Nn / 128, Cc / 128, Bsz), 256>>>(wh + 3 * Cc * Cc, bo, x, out);
}

// round 13
// speedup vs baseline: 1.2197x; 1.0411x over previous
#include <cuda_runtime.h>
#include <cuda_fp16.h>
#include <cstdint>

#define Bsz 2
#define Cc  256
#define Nn  4096
#define Hh  8
#define Gg  8
#define CPG 32
#define EPSv 1e-5f
// log2(e)/sqrt(32)
#define CEXP 0.25503486f

__device__ float  g_scale[Bsz * Cc];
__device__ float  g_shift[Bsz * Cc];
__device__ float  g_part[Bsz * Gg * 8 * 2];
__device__ __half g_XNh[Bsz * Cc * Nn];
__device__ __half g_Wh[4 * Cc * Cc];
__device__ __half g_Qh[Bsz * Cc * Nn];
__device__ __half g_Kh[Bsz * Cc * Nn];
__device__ __half g_Vh[Bsz * Cc * Nn];
__device__ __half g_AOh[Bsz * Cc * Nn];

// attention smem layout (halves): sK[3][32][72], sV[3][32][72], sQ[32][520]
#define SK_OFF 0
#define SV_OFF 6912
#define SQ_OFF 13824
#define SQ_STRIDE 520
#define ATTN_SMEM_BYTES ((13824 + 32 * 520) * 2)

// ---------------------------------------------------------------------------
// helpers
// ---------------------------------------------------------------------------
__device__ __forceinline__ uint32_t smem_u32(const void* p) {
    uint32_t a;
    asm("{ .reg .u64 t; cvta.to.shared.u64 t, %1; cvt.u32.u64 %0, t; }"
        : "=r"(a) : "l"(p));
    return a;
}
__device__ __forceinline__ void ldsm_x4(uint32_t r[4], uint32_t a) {
    asm volatile("ldmatrix.sync.aligned.m8n8.x4.shared.b16 {%0,%1,%2,%3}, [%4];"
                 : "=r"(r[0]), "=r"(r[1]), "=r"(r[2]), "=r"(r[3]) : "r"(a));
}
__device__ __forceinline__ void ldsm_x4t(uint32_t r[4], uint32_t a) {
    asm volatile("ldmatrix.sync.aligned.m8n8.x4.trans.shared.b16 {%0,%1,%2,%3}, [%4];"
                 : "=r"(r[0]), "=r"(r[1]), "=r"(r[2]), "=r"(r[3]) : "r"(a));
}
__device__ __forceinline__ void mma16816(float c[4], const uint32_t a[4],
                                         const uint32_t b0, const uint32_t b1) {
    asm volatile(
        "mma.sync.aligned.m16n8k16.row.col.f32.f16.f16.f32 "
        "{%0,%1,%2,%3}, {%4,%5,%6,%7}, {%8,%9}, {%0,%1,%2,%3};"
        : "+f"(c[0]), "+f"(c[1]), "+f"(c[2]), "+f"(c[3])
        : "r"(a[0]), "r"(a[1]), "r"(a[2]), "r"(a[3]), "r"(b0), "r"(b1));
}
__device__ __forceinline__ uint32_t exp2h2(float lo, float hi) {
    uint32_t d;
    asm("{ .reg .b32 t;\n\t"
        "cvt.rn.f16x2.f32 t, %2, %1;\n\t"
        "ex2.approx.f16x2 %0, t; }"
        : "=r"(d) : "f"(lo), "f"(hi));
    return d;
}
__device__ __forceinline__ uint32_t packh2(float a, float b) {
    __half2 h = __floats2half2_rn(a, b);
    return *(uint32_t*)&h;
}
__device__ __forceinline__ void cp16(uint32_t dst, const void* src) {
    asm volatile("cp.async.cg.shared.global [%0], [%1], 16;"
                 :: "r"(dst), "l"(src) : "memory");
}
#define CP_COMMIT() asm volatile("cp.async.commit_group;" ::: "memory")
#define CP_WAIT2()  asm volatile("cp.async.wait_group 2;" ::: "memory")
#define CP_WAIT1()  asm volatile("cp.async.wait_group 1;" ::: "memory")
#define CP_WAIT0()  asm volatile("cp.async.wait_group 0;" ::: "memory")

// ---------------------------------------------------------------------------
// Kernel 1a: GroupNorm partial sums
// ---------------------------------------------------------------------------
__global__ void gn_part_kernel(const float* __restrict__ x) {
    int bg = blockIdx.x >> 3, slice = blockIdx.x & 7;
    int b = bg / Gg, g = bg % Gg;
    const float4* xp = (const float4*)(x + ((size_t)b * Cc + g * CPG) * Nn)
                     + slice * (CPG * Nn / 4 / 8);
    const int n4 = CPG * Nn / 4 / 8;

    float s = 0.f, ss = 0.f;
    for (int i = threadIdx.x; i < n4; i += 256) {
        float4 v = xp[i];
        s  += v.x + v.y + v.z + v.w;
        ss += v.x * v.x + v.y * v.y + v.z * v.z + v.w * v.w;
    }
    __shared__ float rs[8], rss[8];
    #pragma unroll
    for (int off = 16; off; off >>= 1) {
        s  += __shfl_down_sync(0xffffffffu, s, off);
        ss += __shfl_down_sync(0xffffffffu, ss, off);
    }
    int lane = threadIdx.x & 31, wid = threadIdx.x >> 5;
    if (lane == 0) { rs[wid] = s; rss[wid] = ss; }
    __syncthreads();
    if (threadIdx.x < 8) {
        s = rs[threadIdx.x]; ss = rss[threadIdx.x];
        #pragma unroll
        for (int off = 4; off; off >>= 1) {
            s  += __shfl_down_sync(0xffu, s, off);
            ss += __shfl_down_sync(0xffu, ss, off);
        }
        if (threadIdx.x == 0) {
            g_part[(bg * 8 + slice) * 2 + 0] = s;
            g_part[(bg * 8 + slice) * 2 + 1] = ss;
        }
    }
}

// ---------------------------------------------------------------------------
// Kernel 1b: finalize
// ---------------------------------------------------------------------------
__global__ void gn_fin_kernel(const float* __restrict__ w,
                              const float* __restrict__ bias) {
    int t = threadIdx.x;
    int c = t & 255;
    int bg = t >> 5;
    float s = 0.f, ss = 0.f;
    #pragma unroll
    for (int i = 0; i < 8; i++) {
        s  += g_part[(bg * 8 + i) * 2 + 0];
        ss += g_part[(bg * 8 + i) * 2 + 1];
    }
    const float inv = 1.f / (float)(CPG * Nn);
    float mu = s * inv;
    float var = ss * inv - mu * mu;
    float rstd = rsqrtf(var + EPSv);
    float sc = rstd * w[c];
    g_scale[t] = sc;
    g_shift[t] = bias[c] - mu * sc;
}

// ---------------------------------------------------------------------------
// Kernel 2: normalize -> fp16
// ---------------------------------------------------------------------------
__global__ void normalize_kernel(const float* __restrict__ x) {
    int base = blockIdx.x * 512 + threadIdx.x;
    #pragma unroll
    for (int u = 0; u < 2; u++) {
        int i = base + u * 256;
        int bc = i >> 10;
        float sc = g_scale[bc], sh = g_shift[bc];
        float4 v = ((const float4*)x)[i];
        uint2 o;
        o.x = packh2(fmaf(v.x, sc, sh), fmaf(v.y, sc, sh));
        o.y = packh2(fmaf(v.z, sc, sh), fmaf(v.w, sc, sh));
        ((uint2*)g_XNh)[i] = o;
    }
}

// ---------------------------------------------------------------------------
// Kernel 2b: weights -> fp16
// ---------------------------------------------------------------------------
__global__ void wconv_kernel(const float* __restrict__ w0, const float* __restrict__ w1,
                             const float* __restrict__ w2, const float* __restrict__ w3) {
    int i = blockIdx.x * blockDim.x + threadIdx.x;
    int sel = i >> 14;
    const float* w = (sel == 0) ? w0 : (sel == 1) ? w1 : (sel == 2) ? w2 : w3;
    float4 v = ((const float4*)w)[i & 16383];
    uint2 u;
    u.x = packh2(v.x, v.y);
    u.y = packh2(v.z, v.w);
    ((uint2*)g_Wh)[i] = u;
}

// ---------------------------------------------------------------------------
// Kernel 3: stacked QKV GEMM (M=768). BM=128 BN=128 BK=32, 2-stage cp.async.
// ---------------------------------------------------------------------------
__global__ void __launch_bounds__(256)
gemm_qkv(const __half* __restrict__ Wp,
         const float* __restrict__ bq, const float* __restrict__ bk,
         const float* __restrict__ bv) {
    __shared__ __align__(16) __half sA[2][128][40];
    __shared__ __align__(16) __half sB[2][32][136];

    int bz = blockIdx.z;
    const __half* X = g_XNh + (size_t)bz * Cc * Nn;
    int n0 = blockIdx.x * 128;
    int mg = blockIdx.y * 128;
    int which = mg >> 8;
    int m0 = mg & 255;
    int tid = threadIdx.x, lane = tid & 31, wid = tid >> 5;
    int wm = wid & 1, wn = wid >> 1;
    int g = lane >> 2, tg = lane & 3;
    int r7 = lane & 7, sel = lane >> 3, r15 = lane & 15, hi8 = lane >> 4;

    float c[4][4][4] = {};

    auto issue = [&](int kt, int buf) {
        int k0 = kt * 32;
        #pragma unroll
        for (int i = 0; i < 2; i++) {
            int idx = tid + i * 256;
            int arow = idx >> 2, acol = (idx & 3) << 3;
            cp16(smem_u32(&sA[buf][arow][acol]),
                 Wp + (size_t)(mg + arow) * Cc + k0 + acol);
            int brow = idx >> 4, bcc = (idx & 15) << 3;
            cp16(smem_u32(&sB[buf][brow & 31][bcc]),
                 X + (size_t)(k0 + (brow & 31)) * Nn + n0 + bcc);
        }
    };

    issue(0, 0); CP_COMMIT();

    for (int kt = 0; kt < 8; kt++) {
        int cur = kt & 1;
        if (kt + 1 < 8) { issue(kt + 1, cur ^ 1); CP_COMMIT(); CP_WAIT1(); }
        else            { CP_WAIT0(); }
        __syncthreads();

        #pragma unroll
        for (int ks = 0; ks < 2; ks++) {
            uint32_t a[4][4], bf[2][4];
            #pragma unroll
            for (int mt = 0; mt < 4; mt++)
                ldsm_x4(a[mt],
                        smem_u32(&sA[cur][wm * 64 + mt * 16 + (sel & 1) * 8 + r7]
                                        [ks * 16 + (sel >> 1) * 8]));
            #pragma unroll
            for (int jp = 0; jp < 2; jp++)
                ldsm_x4t(bf[jp],
                         smem_u32(&sB[cur][ks * 16 + r15][wn * 32 + jp * 16 + hi8 * 8]));
            #pragma unroll
            for (int mt = 0; mt < 4; mt++)
                #pragma unroll
                for (int jp = 0; jp < 2; jp++) {
                    mma16816(c[mt][jp * 2 + 0], a[mt], bf[jp][0], bf[jp][1]);
                    mma16816(c[mt][jp * 2 + 1], a[mt], bf[jp][2], bf[jp][3]);
                }
        }
        __syncthreads();
    }

    __half* outp = ((which == 0) ? g_Qh : (which == 1) ? g_Kh : g_Vh)
                 + (size_t)bz * Cc * Nn;
    const float* bp = (which == 0) ? bq : (which == 1) ? bk : bv;
    #pragma unroll
    for (int mt = 0; mt < 4; mt++) {
        int m = m0 + wm * 64 + mt * 16 + g;
        float b0 = bp[m], b1 = bp[m + 8];
        #pragma unroll
        for (int jt = 0; jt < 4; jt++) {
            int n = n0 + wn * 32 + jt * 8 + 2 * tg;
            *(__half2*)(outp + (size_t)m * Nn + n) =
                __floats2half2_rn(c[mt][jt][0] + b0, c[mt][jt][1] + b0);
            *(__half2*)(outp + (size_t)(m + 8) * Nn + n) =
                __floats2half2_rn(c[mt][jt][2] + b1, c[mt][jt][3] + b1);
        }
    }
}

// ---------------------------------------------------------------------------
// Kernel 5: output projection GEMM + residual, fp32 out.
// ---------------------------------------------------------------------------
__global__ void __launch_bounds__(256)
gemm_o(const __half* __restrict__ Wp, const float* __restrict__ bias,
       const float* __restrict__ resid, float* __restrict__ Out) {
    __shared__ __align__(16) __half sA[2][128][40];
    __shared__ __align__(16) __half sB[2][32][136];

    int bz = blockIdx.z;
    const __half* X = g_AOh + (size_t)bz * Cc * Nn;
    int n0 = blockIdx.x * 128, m0 = blockIdx.y * 128;
    int tid = threadIdx.x, lane = tid & 31, wid = tid >> 5;
    int wm = wid & 1, wn = wid >> 1;
    int g = lane >> 2, tg = lane & 3;
    int r7 = lane & 7, sel = lane >> 3, r15 = lane & 15, hi8 = lane >> 4;

    float c[4][4][4] = {};

    auto issue = [&](int kt, int buf) {
        int k0 = kt * 32;
        #pragma unroll
        for (int i = 0; i < 2; i++) {
            int idx = tid + i * 256;
            int arow = idx >> 2, acol = (idx & 3) << 3;
            cp16(smem_u32(&sA[buf][arow][acol]),
                 Wp + (size_t)(m0 + arow) * Cc + k0 + acol);
            int brow = idx >> 4, bcc = (idx & 15) << 3;
            cp16(smem_u32(&sB[buf][brow & 31][bcc]),
                 X + (size_t)(k0 + (brow & 31)) * Nn + n0 + bcc);
        }
    };

    issue(0, 0); CP_COMMIT();

    for (int kt = 0; kt < 8; kt++) {
        int cur = kt & 1;
        if (kt + 1 < 8) { issue(kt + 1, cur ^ 1); CP_COMMIT(); CP_WAIT1(); }
        else            { CP_WAIT0(); }
        __syncthreads();

        #pragma unroll
        for (int ks = 0; ks < 2; ks++) {
            uint32_t a[4][4], bf[2][4];
            #pragma unroll
            for (int mt = 0; mt < 4; mt++)
                ldsm_x4(a[mt],
                        smem_u32(&sA[cur][wm * 64 + mt * 16 + (sel & 1) * 8 + r7]
                                        [ks * 16 + (sel >> 1) * 8]));
            #pragma unroll
            for (int jp = 0; jp < 2; jp++)
                ldsm_x4t(bf[jp],
                         smem_u32(&sB[cur][ks * 16 + r15][wn * 32 + jp * 16 + hi8 * 8]));
            #pragma unroll
            for (int mt = 0; mt < 4; mt++)
                #pragma unroll
                for (int jp = 0; jp < 2; jp++) {
                    mma16816(c[mt][jp * 2 + 0], a[mt], bf[jp][0], bf[jp][1]);
                    mma16816(c[mt][jp * 2 + 1], a[mt], bf[jp][2], bf[jp][3]);
                }
        }
        __syncthreads();
    }

    #pragma unroll
    for (int mt = 0; mt < 4; mt++) {
        int m = m0 + wm * 64 + mt * 16 + g;
        float b0 = bias[m], b1 = bias[m + 8];
        #pragma unroll
        for (int jt = 0; jt < 4; jt++) {
            int n = n0 + wn * 32 + jt * 8 + 2 * tg;
            size_t o0 = ((size_t)bz * Cc + m) * Nn + n;
            size_t o1 = ((size_t)bz * Cc + m + 8) * Nn + n;
            float2 r0 = *(const float2*)(resid + o0);
            float2 r1 = *(const float2*)(resid + o1);
            *(float2*)(Out + o0) = make_float2(c[mt][jt][0] + b0 + r0.x,
                                               c[mt][jt][1] + b0 + r0.y);
            *(float2*)(Out + o1) = make_float2(c[mt][jt][2] + b1 + r1.x,
                                               c[mt][jt][3] + b1 + r1.y);
        }
    }
}

// ---------------------------------------------------------------------------
// Kernel 4: HMMA flash attention. 512 queries/block -> grid 128 (1 wave,
// perfectly balanced, 1 block/SM). 8 warps x 64 queries (4 m-tiles).
// Dynamic smem: sK/sV 3-stage + sQ staging.
// ---------------------------------------------------------------------------
extern __shared__ __half s_attn[];

__global__ void __launch_bounds__(256, 1)
attn_kernel() {
    __half* sK = s_attn + SK_OFF;   // [3][32][72]
    __half* sV = s_attn + SV_OFF;   // [3][32][72]
    __half* sQ = s_attn + SQ_OFF;   // [32][520]

    int tid = threadIdx.x, lane = tid & 31, wid = tid >> 5;
    int b = blockIdx.z, h = blockIdx.y;
    int q0 = blockIdx.x * 512;
    size_t base = ((size_t)b * Cc + h * 32) * Nn;
    const __half* Qg = g_Qh + base;
    const __half* Kg = g_Kh + base;
    const __half* Vg = g_Vh + base;
    int g = lane >> 2, tg = lane & 3;
    int r7 = lane & 7, sel = lane >> 3, r15 = lane & 15, hi8 = lane >> 4;

    auto kv_off = [](int buf, int row, int col) {
        return buf * (32 * 72) + row * 72 + col;
    };
    auto issue = [&](int t, int buf) {
        int row = tid >> 3, cc = (tid & 7) << 3;
        size_t off = (size_t)row * Nn + t * 64 + cc;
        cp16(smem_u32(sK + kv_off(buf, row, cc)), Kg + off);
        cp16(smem_u32(sV + kv_off(buf, row, cc)), Vg + off);
    };

    issue(0, 0); CP_COMMIT();
    issue(1, 1); CP_COMMIT();

    // Q staging: 32 d-rows x 512 queries
    #pragma unroll
    for (int i = 0; i < 8; i++) {
        int idx = tid + i * 256;
        int row = idx >> 6, cc = (idx & 63) << 3;
        *(uint4*)(sQ + row * SQ_STRIDE + cc) =
            *(const uint4*)(Qg + (size_t)row * Nn + q0 + cc);
    }
    __syncthreads();
    uint32_t qa[4][2][4];
    const __half2 cs2 = __float2half2_rn(CEXP);
    #pragma unroll
    for (int mt = 0; mt < 4; mt++)
        #pragma unroll
        for (int s = 0; s < 2; s++) {
            ldsm_x4t(qa[mt][s],
                     smem_u32(sQ + (s * 16 + (sel >> 1) * 8 + r7) * SQ_STRIDE
                                 + wid * 64 + mt * 16 + (sel & 1) * 8));
            #pragma unroll
            for (int i = 0; i < 4; i++) {
                __half2 t2 = __hmul2(*(__half2*)&qa[mt][s][i], cs2);
                qa[mt][s][i] = *(uint32_t*)&t2;
            }
        }

    float oc[4][4][4] = {};
    float rc[4][4] = {};
    const uint32_t ONES = 0x3C003C00u;

    for (int t = 0; t < Nn / 64; t++) {
        int cur = t % 3;
        if (t + 2 < Nn / 64)      { issue(t + 2, (t + 2) % 3); CP_COMMIT(); CP_WAIT2(); }
        else if (t + 1 < Nn / 64) { CP_WAIT1(); }
        else                      { CP_WAIT0(); }
        __syncthreads();

        #pragma unroll
        for (int jp = 0; jp < 4; jp++) {
            uint32_t kf[2][4];
            #pragma unroll
            for (int s = 0; s < 2; s++)
                ldsm_x4t(kf[s], smem_u32(sK + kv_off(cur, s * 16 + r15,
                                                     jp * 16 + hi8 * 8)));
            uint32_t pa[4][4];
            #pragma unroll
            for (int mt = 0; mt < 4; mt++)
                #pragma unroll
                for (int j2 = 0; j2 < 2; j2++) {
                    float sc[4] = {0.f, 0.f, 0.f, 0.f};
                    mma16816(sc, qa[mt][0], kf[0][j2 * 2], kf[0][j2 * 2 + 1]);
                    mma16816(sc, qa[mt][1], kf[1][j2 * 2], kf[1][j2 * 2 + 1]);
                    pa[mt][j2 * 2 + 0] = exp2h2(sc[0], sc[1]);
                    pa[mt][j2 * 2 + 1] = exp2h2(sc[2], sc[3]);
                }
            #pragma unroll
            for (int mt = 0; mt < 4; mt++)
                mma16816(rc[mt], pa[mt], ONES, ONES);
            #pragma unroll
            for (int dnp = 0; dnp < 2; dnp++) {
                uint32_t vf[4];
                ldsm_x4(vf, smem_u32(sV + kv_off(cur, dnp * 16 + hi8 * 8 + r7,
                                                 jp * 16 + ((lane >> 3) & 1) * 8)));
                #pragma unroll
                for (int mt = 0; mt < 4; mt++) {
                    mma16816(oc[mt][dnp * 2],     pa[mt], vf[0], vf[1]);
                    mma16816(oc[mt][dnp * 2 + 1], pa[mt], vf[2], vf[3]);
                }
            }
        }
        __syncthreads();
    }

    // normalize, stage O into sQ, store
    #pragma unroll
    for (int mt = 0; mt < 4; mt++) {
        float inv0 = 1.f / rc[mt][0], inv1 = 1.f / rc[mt][2];
        int qc = wid * 64 + mt * 16;
        #pragma unroll
        for (int dn = 0; dn < 4; dn++) {
            int d0 = dn * 8 + 2 * tg;
            sQ[d0 * SQ_STRIDE + qc + g]           = __float2half(oc[mt][dn][0] * inv0);
            sQ[(d0 + 1) * SQ_STRIDE + qc + g]     = __float2half(oc[mt][dn][1] * inv0);
            sQ[d0 * SQ_STRIDE + qc + g + 8]       = __float2half(oc[mt][dn][2] * inv1);
            sQ[(d0 + 1) * SQ_STRIDE + qc + g + 8] = __float2half(oc[mt][dn][3] * inv1);
        }
    }
    __syncthreads();
    __half* AO = g_AOh + base;
    #pragma unroll
    for (int i = 0; i < 8; i++) {
        int idx = tid + i * 256;
        int row = idx >> 6, cc = (idx & 63) << 3;
        *(uint4*)(AO + (size_t)row * Nn + q0 + cc) =
            *(uint4*)(sQ + row * SQ_STRIDE + cc);
    }
}

// ---------------------------------------------------------------------------
// Launch
// ---------------------------------------------------------------------------
extern "C" void kernel_launch(void* const* d_in, const int* in_sizes, int n_in,
                              void* d_out, int out_size) {
    const float* x    = (const float*)d_in[0];
    const float* gn_w = (const float*)d_in[1];
    const float* gn_b = (const float*)d_in[2];
    const float* wq   = (const float*)d_in[3];
    const float* bq   = (const float*)d_in[4];
    const float* wk   = (const float*)d_in[5];
    const float* bk   = (const float*)d_in[6];
    const float* wv   = (const float*)d_in[7];
    const float* bv   = (const float*)d_in[8];
    const float* wo   = (const float*)d_in[9];
    const float* bo   = (const float*)d_in[10];
    float* out = (float*)d_out;

    __half* wh;
    cudaGetSymbolAddress((void**)&wh, g_Wh);

    static bool attr_set = false;
    if (!attr_set) {
        cudaFuncSetAttribute(attn_kernel,
                             cudaFuncAttributeMaxDynamicSharedMemorySize,
                             ATTN_SMEM_BYTES);
        attr_set = true;
    }

    wconv_kernel<<<256, 256>>>(wq, wk, wv, wo);
    gn_part_kernel<<<128, 256>>>(x);
    gn_fin_kernel<<<1, 512>>>(gn_w, gn_b);
    normalize_kernel<<<(Bsz * Cc * Nn / 4) / 512, 256>>>(x);

    gemm_qkv<<<dim3(Nn / 128, 6, Bsz), 256>>>(wh, bq, bk, bv);

    attn_kernel<<<dim3(Nn / 512, Hh, Bsz), 256, ATTN_SMEM_BYTES>>>();

    gemm_o<<<dim3(Nn / 128, Cc / 128, Bsz), 256>>>(wh + 3 * Cc * Cc, bo, x, out);
}

// round 14
// speedup vs baseline: 1.2745x; 1.0449x over previous
#include <cuda_runtime.h>
#include <cuda_fp16.h>
#include <cstdint>

#define Bsz 2
#define Cc  256
#define Nn  4096
#define Hh  8
#define Gg  8
#define CPG 32
#define EPSv 1e-5f
// log2(e)/sqrt(32)
#define CEXP 0.25503486f

__device__ float  g_scale[Bsz * Cc];
__device__ float  g_shift[Bsz * Cc];
__device__ float  g_part[Bsz * Gg * 8 * 2];
__device__ __half g_XNh[Bsz * Cc * Nn];
__device__ __half g_Wh[4 * Cc * Cc];
__device__ __half g_Qh[Bsz * Cc * Nn];
__device__ __half g_Kh[Bsz * Cc * Nn];
__device__ __half g_Vh[Bsz * Cc * Nn];
__device__ __half g_AOh[Bsz * Cc * Nn];

// attention smem (halves): sK[4][32][136], sV[4][32][136], sQ[32][520]
#define KV_BUF   (32 * 136)
#define SK_OFF   0
#define SV_OFF   (4 * KV_BUF)
#define SQ_OFF   (8 * KV_BUF)
#define SQ_STRIDE 520
#define ATTN_SMEM_BYTES ((8 * KV_BUF + 32 * 520) * 2)

// ---------------------------------------------------------------------------
// helpers
// ---------------------------------------------------------------------------
__device__ __forceinline__ uint32_t smem_u32(const void* p) {
    uint32_t a;
    asm("{ .reg .u64 t; cvta.to.shared.u64 t, %1; cvt.u32.u64 %0, t; }"
        : "=r"(a) : "l"(p));
    return a;
}
__device__ __forceinline__ void ldsm_x4(uint32_t r[4], uint32_t a) {
    asm volatile("ldmatrix.sync.aligned.m8n8.x4.shared.b16 {%0,%1,%2,%3}, [%4];"
                 : "=r"(r[0]), "=r"(r[1]), "=r"(r[2]), "=r"(r[3]) : "r"(a));
}
__device__ __forceinline__ void ldsm_x4t(uint32_t r[4], uint32_t a) {
    asm volatile("ldmatrix.sync.aligned.m8n8.x4.trans.shared.b16 {%0,%1,%2,%3}, [%4];"
                 : "=r"(r[0]), "=r"(r[1]), "=r"(r[2]), "=r"(r[3]) : "r"(a));
}
__device__ __forceinline__ void mma16816(float c[4], const uint32_t a[4],
                                         const uint32_t b0, const uint32_t b1) {
    asm volatile(
        "mma.sync.aligned.m16n8k16.row.col.f32.f16.f16.f32 "
        "{%0,%1,%2,%3}, {%4,%5,%6,%7}, {%8,%9}, {%0,%1,%2,%3};"
        : "+f"(c[0]), "+f"(c[1]), "+f"(c[2]), "+f"(c[3])
        : "r"(a[0]), "r"(a[1]), "r"(a[2]), "r"(a[3]), "r"(b0), "r"(b1));
}
__device__ __forceinline__ uint32_t exp2h2(float lo, float hi) {
    uint32_t d;
    asm("{ .reg .b32 t;\n\t"
        "cvt.rn.f16x2.f32 t, %2, %1;\n\t"
        "ex2.approx.f16x2 %0, t; }"
        : "=r"(d) : "f"(lo), "f"(hi));
    return d;
}
__device__ __forceinline__ uint32_t packh2(float a, float b) {
    __half2 h = __floats2half2_rn(a, b);
    return *(uint32_t*)&h;
}
__device__ __forceinline__ void cp16(uint32_t dst, const void* src) {
    asm volatile("cp.async.cg.shared.global [%0], [%1], 16;"
                 :: "r"(dst), "l"(src) : "memory");
}
#define CP_COMMIT() asm volatile("cp.async.commit_group;" ::: "memory")
#define CP_WAIT2()  asm volatile("cp.async.wait_group 2;" ::: "memory")
#define CP_WAIT1()  asm volatile("cp.async.wait_group 1;" ::: "memory")
#define CP_WAIT0()  asm volatile("cp.async.wait_group 0;" ::: "memory")

// ---------------------------------------------------------------------------
// Kernel 1a: GroupNorm partial sums
// ---------------------------------------------------------------------------
__global__ void gn_part_kernel(const float* __restrict__ x) {
    int bg = blockIdx.x >> 3, slice = blockIdx.x & 7;
    int b = bg / Gg, g = bg % Gg;
    const float4* xp = (const float4*)(x + ((size_t)b * Cc + g * CPG) * Nn)
                     + slice * (CPG * Nn / 4 / 8);
    const int n4 = CPG * Nn / 4 / 8;

    float s = 0.f, ss = 0.f;
    for (int i = threadIdx.x; i < n4; i += 256) {
        float4 v = xp[i];
        s  += v.x + v.y + v.z + v.w;
        ss += v.x * v.x + v.y * v.y + v.z * v.z + v.w * v.w;
    }
    __shared__ float rs[8], rss[8];
    #pragma unroll
    for (int off = 16; off; off >>= 1) {
        s  += __shfl_down_sync(0xffffffffu, s, off);
        ss += __shfl_down_sync(0xffffffffu, ss, off);
    }
    int lane = threadIdx.x & 31, wid = threadIdx.x >> 5;
    if (lane == 0) { rs[wid] = s; rss[wid] = ss; }
    __syncthreads();
    if (threadIdx.x < 8) {
        s = rs[threadIdx.x]; ss = rss[threadIdx.x];
        #pragma unroll
        for (int off = 4; off; off >>= 1) {
            s  += __shfl_down_sync(0xffu, s, off);
            ss += __shfl_down_sync(0xffu, ss, off);
        }
        if (threadIdx.x == 0) {
            g_part[(bg * 8 + slice) * 2 + 0] = s;
            g_part[(bg * 8 + slice) * 2 + 1] = ss;
        }
    }
}

// ---------------------------------------------------------------------------
// Kernel 1b: finalize
// ---------------------------------------------------------------------------
__global__ void gn_fin_kernel(const float* __restrict__ w,
                              const float* __restrict__ bias) {
    int t = threadIdx.x;
    int c = t & 255;
    int bg = t >> 5;
    float s = 0.f, ss = 0.f;
    #pragma unroll
    for (int i = 0; i < 8; i++) {
        s  += g_part[(bg * 8 + i) * 2 + 0];
        ss += g_part[(bg * 8 + i) * 2 + 1];
    }
    const float inv = 1.f / (float)(CPG * Nn);
    float mu = s * inv;
    float var = ss * inv - mu * mu;
    float rstd = rsqrtf(var + EPSv);
    float sc = rstd * w[c];
    g_scale[t] = sc;
    g_shift[t] = bias[c] - mu * sc;
}

// ---------------------------------------------------------------------------
// Kernel 2: normalize -> fp16
// ---------------------------------------------------------------------------
__global__ void normalize_kernel(const float* __restrict__ x) {
    int base = blockIdx.x * 512 + threadIdx.x;
    #pragma unroll
    for (int u = 0; u < 2; u++) {
        int i = base + u * 256;
        int bc = i >> 10;
        float sc = g_scale[bc], sh = g_shift[bc];
        float4 v = ((const float4*)x)[i];
        uint2 o;
        o.x = packh2(fmaf(v.x, sc, sh), fmaf(v.y, sc, sh));
        o.y = packh2(fmaf(v.z, sc, sh), fmaf(v.w, sc, sh));
        ((uint2*)g_XNh)[i] = o;
    }
}

// ---------------------------------------------------------------------------
// Kernel 2b: weights -> fp16
// ---------------------------------------------------------------------------
__global__ void wconv_kernel(const float* __restrict__ w0, const float* __restrict__ w1,
                             const float* __restrict__ w2, const float* __restrict__ w3) {
    int i = blockIdx.x * blockDim.x + threadIdx.x;
    int sel = i >> 14;
    const float* w = (sel == 0) ? w0 : (sel == 1) ? w1 : (sel == 2) ? w2 : w3;
    float4 v = ((const float4*)w)[i & 16383];
    uint2 u;
    u.x = packh2(v.x, v.y);
    u.y = packh2(v.z, v.w);
    ((uint2*)g_Wh)[i] = u;
}

// ---------------------------------------------------------------------------
// Kernel 3: stacked QKV GEMM (M=768). BM=128 BN=128 BK=32, 2-stage cp.async.
// ---------------------------------------------------------------------------
__global__ void __launch_bounds__(256)
gemm_qkv(const __half* __restrict__ Wp,
         const float* __restrict__ bq, const float* __restrict__ bk,
         const float* __restrict__ bv) {
    __shared__ __align__(16) __half sA[2][128][40];
    __shared__ __align__(16) __half sB[2][32][136];

    int bz = blockIdx.z;
    const __half* X = g_XNh + (size_t)bz * Cc * Nn;
    int n0 = blockIdx.x * 128;
    int mg = blockIdx.y * 128;
    int which = mg >> 8;
    int m0 = mg & 255;
    int tid = threadIdx.x, lane = tid & 31, wid = tid >> 5;
    int wm = wid & 1, wn = wid >> 1;
    int g = lane >> 2, tg = lane & 3;
    int r7 = lane & 7, sel = lane >> 3, r15 = lane & 15, hi8 = lane >> 4;

    float c[4][4][4] = {};

    auto issue = [&](int kt, int buf) {
        int k0 = kt * 32;
        #pragma unroll
        for (int i = 0; i < 2; i++) {
            int idx = tid + i * 256;
            int arow = idx >> 2, acol = (idx & 3) << 3;
            cp16(smem_u32(&sA[buf][arow][acol]),
                 Wp + (size_t)(mg + arow) * Cc + k0 + acol);
            int brow = idx >> 4, bcc = (idx & 15) << 3;
            cp16(smem_u32(&sB[buf][brow & 31][bcc]),
                 X + (size_t)(k0 + (brow & 31)) * Nn + n0 + bcc);
        }
    };

    issue(0, 0); CP_COMMIT();

    for (int kt = 0; kt < 8; kt++) {
        int cur = kt & 1;
        if (kt + 1 < 8) { issue(kt + 1, cur ^ 1); CP_COMMIT(); CP_WAIT1(); }
        else            { CP_WAIT0(); }
        __syncthreads();

        #pragma unroll
        for (int ks = 0; ks < 2; ks++) {
            uint32_t a[4][4], bf[2][4];
            #pragma unroll
            for (int mt = 0; mt < 4; mt++)
                ldsm_x4(a[mt],
                        smem_u32(&sA[cur][wm * 64 + mt * 16 + (sel & 1) * 8 + r7]
                                        [ks * 16 + (sel >> 1) * 8]));
            #pragma unroll
            for (int jp = 0; jp < 2; jp++)
                ldsm_x4t(bf[jp],
                         smem_u32(&sB[cur][ks * 16 + r15][wn * 32 + jp * 16 + hi8 * 8]));
            #pragma unroll
            for (int mt = 0; mt < 4; mt++)
                #pragma unroll
                for (int jp = 0; jp < 2; jp++) {
                    mma16816(c[mt][jp * 2 + 0], a[mt], bf[jp][0], bf[jp][1]);
                    mma16816(c[mt][jp * 2 + 1], a[mt], bf[jp][2], bf[jp][3]);
                }
        }
        __syncthreads();
    }

    __half* outp = ((which == 0) ? g_Qh : (which == 1) ? g_Kh : g_Vh)
                 + (size_t)bz * Cc * Nn;
    const float* bp = (which == 0) ? bq : (which == 1) ? bk : bv;
    #pragma unroll
    for (int mt = 0; mt < 4; mt++) {
        int m = m0 + wm * 64 + mt * 16 + g;
        float b0 = bp[m], b1 = bp[m + 8];
        #pragma unroll
        for (int jt = 0; jt < 4; jt++) {
            int n = n0 + wn * 32 + jt * 8 + 2 * tg;
            *(__half2*)(outp + (size_t)m * Nn + n) =
                __floats2half2_rn(c[mt][jt][0] + b0, c[mt][jt][1] + b0);
            *(__half2*)(outp + (size_t)(m + 8) * Nn + n) =
                __floats2half2_rn(c[mt][jt][2] + b1, c[mt][jt][3] + b1);
        }
    }
}

// ---------------------------------------------------------------------------
// Kernel 5: output projection GEMM + residual, fp32 out.
// ---------------------------------------------------------------------------
__global__ void __launch_bounds__(256)
gemm_o(const __half* __restrict__ Wp, const float* __restrict__ bias,
       const float* __restrict__ resid, float* __restrict__ Out) {
    __shared__ __align__(16) __half sA[2][128][40];
    __shared__ __align__(16) __half sB[2][32][136];

    int bz = blockIdx.z;
    const __half* X = g_AOh + (size_t)bz * Cc * Nn;
    int n0 = blockIdx.x * 128, m0 = blockIdx.y * 128;
    int tid = threadIdx.x, lane = tid & 31, wid = tid >> 5;
    int wm = wid & 1, wn = wid >> 1;
    int g = lane >> 2, tg = lane & 3;
    int r7 = lane & 7, sel = lane >> 3, r15 = lane & 15, hi8 = lane >> 4;

    float c[4][4][4] = {};

    auto issue = [&](int kt, int buf) {
        int k0 = kt * 32;
        #pragma unroll
        for (int i = 0; i < 2; i++) {
            int idx = tid + i * 256;
            int arow = idx >> 2, acol = (idx & 3) << 3;
            cp16(smem_u32(&sA[buf][arow][acol]),
                 Wp + (size_t)(m0 + arow) * Cc + k0 + acol);
            int brow = idx >> 4, bcc = (idx & 15) << 3;
            cp16(smem_u32(&sB[buf][brow & 31][bcc]),
                 X + (size_t)(k0 + (brow & 31)) * Nn + n0 + bcc);
        }
    };

    issue(0, 0); CP_COMMIT();

    for (int kt = 0; kt < 8; kt++) {
        int cur = kt & 1;
        if (kt + 1 < 8) { issue(kt + 1, cur ^ 1); CP_COMMIT(); CP_WAIT1(); }
        else            { CP_WAIT0(); }
        __syncthreads();

        #pragma unroll
        for (int ks = 0; ks < 2; ks++) {
            uint32_t a[4][4], bf[2][4];
            #pragma unroll
            for (int mt = 0; mt < 4; mt++)
                ldsm_x4(a[mt],
                        smem_u32(&sA[cur][wm * 64 + mt * 16 + (sel & 1) * 8 + r7]
                                        [ks * 16 + (sel >> 1) * 8]));
            #pragma unroll
            for (int jp = 0; jp < 2; jp++)
                ldsm_x4t(bf[jp],
                         smem_u32(&sB[cur][ks * 16 + r15][wn * 32 + jp * 16 + hi8 * 8]));
            #pragma unroll
            for (int mt = 0; mt < 4; mt++)
                #pragma unroll
                for (int jp = 0; jp < 2; jp++) {
                    mma16816(c[mt][jp * 2 + 0], a[mt], bf[jp][0], bf[jp][1]);
                    mma16816(c[mt][jp * 2 + 1], a[mt], bf[jp][2], bf[jp][3]);
                }
        }
        __syncthreads();
    }

    #pragma unroll
    for (int mt = 0; mt < 4; mt++) {
        int m = m0 + wm * 64 + mt * 16 + g;
        float b0 = bias[m], b1 = bias[m + 8];
        #pragma unroll
        for (int jt = 0; jt < 4; jt++) {
            int n = n0 + wn * 32 + jt * 8 + 2 * tg;
            size_t o0 = ((size_t)bz * Cc + m) * Nn + n;
            size_t o1 = ((size_t)bz * Cc + m + 8) * Nn + n;
            float2 r0 = *(const float2*)(resid + o0);
            float2 r1 = *(const float2*)(resid + o1);
            *(float2*)(Out + o0) = make_float2(c[mt][jt][0] + b0 + r0.x,
                                               c[mt][jt][1] + b0 + r0.y);
            *(float2*)(Out + o1) = make_float2(c[mt][jt][2] + b1 + r1.x,
                                               c[mt][jt][3] + b1 + r1.y);
        }
    }
}

// ---------------------------------------------------------------------------
// Kernel 4: HMMA flash attention. 512 q/block, grid 128 = 1 balanced wave.
// Bc=128 keys/tile (32 iterations), 4-stage cp.async ring, ONE barrier/iter:
// issue(t+2) targets buf (t+2)%4 which is never one of the two buffers
// possibly being read ((t-1)%4, t%4) since 2 != -1, 0 (mod 4).
// ---------------------------------------------------------------------------
extern __shared__ __half s_attn[];

__global__ void __launch_bounds__(256, 1)
attn_kernel() {
    __half* sK = s_attn + SK_OFF;   // [4][32][136]
    __half* sV = s_attn + SV_OFF;   // [4][32][136]
    __half* sQ = s_attn + SQ_OFF;   // [32][520]

    int tid = threadIdx.x, lane = tid & 31, wid = tid >> 5;
    int b = blockIdx.z, h = blockIdx.y;
    int q0 = blockIdx.x * 512;
    size_t base = ((size_t)b * Cc + h * 32) * Nn;
    const __half* Qg = g_Qh + base;
    const __half* Kg = g_Kh + base;
    const __half* Vg = g_Vh + base;
    int g = lane >> 2, tg = lane & 3;
    int r7 = lane & 7, sel = lane >> 3, r15 = lane & 15, hi8 = lane >> 4;

    auto kv_off = [](int buf, int row, int col) {
        return buf * KV_BUF + row * 136 + col;
    };
    auto issue = [&](int t, int buf) {
        int row = tid >> 3;
        #pragma unroll
        for (int i = 0; i < 2; i++) {
            int cc = ((tid & 7) << 3) + i * 64;
            size_t off = (size_t)row * Nn + t * 128 + cc;
            cp16(smem_u32(sK + kv_off(buf, row, cc)), Kg + off);
            cp16(smem_u32(sV + kv_off(buf, row, cc)), Vg + off);
        }
    };

    issue(0, 0); CP_COMMIT();
    issue(1, 1); CP_COMMIT();

    // Q staging: 32 d-rows x 512 queries
    #pragma unroll
    for (int i = 0; i < 8; i++) {
        int idx = tid + i * 256;
        int row = idx >> 6, cc = (idx & 63) << 3;
        *(uint4*)(sQ + row * SQ_STRIDE + cc) =
            *(const uint4*)(Qg + (size_t)row * Nn + q0 + cc);
    }
    __syncthreads();
    uint32_t qa[4][2][4];
    const __half2 cs2 = __float2half2_rn(CEXP);
    #pragma unroll
    for (int mt = 0; mt < 4; mt++)
        #pragma unroll
        for (int s = 0; s < 2; s++) {
            ldsm_x4t(qa[mt][s],
                     smem_u32(sQ + (s * 16 + (sel >> 1) * 8 + r7) * SQ_STRIDE
                                 + wid * 64 + mt * 16 + (sel & 1) * 8));
            #pragma unroll
            for (int i = 0; i < 4; i++) {
                __half2 t2 = __hmul2(*(__half2*)&qa[mt][s][i], cs2);
                qa[mt][s][i] = *(uint32_t*)&t2;
            }
        }

    float oc[4][4][4] = {};
    float rc[4][4] = {};
    const uint32_t ONES = 0x3C003C00u;
    const int NT = Nn / 128;   // 32

    for (int t = 0; t < NT; t++) {
        int cur = t & 3;
        if (t + 2 < NT) { issue(t + 2, (t + 2) & 3); CP_COMMIT(); CP_WAIT2(); }
        else if (t + 1 < NT) { CP_WAIT1(); }
        else                 { CP_WAIT0(); }
        __syncthreads();   // the ONLY barrier in the iteration

        #pragma unroll
        for (int jp = 0; jp < 8; jp++) {
            uint32_t kf[2][4];
            #pragma unroll
            for (int s = 0; s < 2; s++)
                ldsm_x4t(kf[s], smem_u32(sK + kv_off(cur, s * 16 + r15,
                                                     jp * 16 + hi8 * 8)));
            uint32_t pa[4][4];
            #pragma unroll
            for (int mt = 0; mt < 4; mt++)
                #pragma unroll
                for (int j2 = 0; j2 < 2; j2++) {
                    float sc[4] = {0.f, 0.f, 0.f, 0.f};
                    mma16816(sc, qa[mt][0], kf[0][j2 * 2], kf[0][j2 * 2 + 1]);
                    mma16816(sc, qa[mt][1], kf[1][j2 * 2], kf[1][j2 * 2 + 1]);
                    pa[mt][j2 * 2 + 0] = exp2h2(sc[0], sc[1]);
                    pa[mt][j2 * 2 + 1] = exp2h2(sc[2], sc[3]);
                }
            #pragma unroll
            for (int mt = 0; mt < 4; mt++)
                mma16816(rc[mt], pa[mt], ONES, ONES);
            #pragma unroll
            for (int dnp = 0; dnp < 2; dnp++) {
                uint32_t vf[4];
                ldsm_x4(vf, smem_u32(sV + kv_off(cur, dnp * 16 + hi8 * 8 + r7,
                                                 jp * 16 + ((lane >> 3) & 1) * 8)));
                #pragma unroll
                for (int mt = 0; mt < 4; mt++) {
                    mma16816(oc[mt][dnp * 2],     pa[mt], vf[0], vf[1]);
                    mma16816(oc[mt][dnp * 2 + 1], pa[mt], vf[2], vf[3]);
                }
            }
        }
    }

    __syncthreads();
    // normalize, stage O into sQ, store
    #pragma unroll
    for (int mt = 0; mt < 4; mt++) {
        float inv0 = 1.f / rc[mt][0], inv1 = 1.f / rc[mt][2];
        int qc = wid * 64 + mt * 16;
        #pragma unroll
        for (int dn = 0; dn < 4; dn++) {
            int d0 = dn * 8 + 2 * tg;
            sQ[d0 * SQ_STRIDE + qc + g]           = __float2half(oc[mt][dn][0] * inv0);
            sQ[(d0 + 1) * SQ_STRIDE + qc + g]     = __float2half(oc[mt][dn][1] * inv0);
            sQ[d0 * SQ_STRIDE + qc + g + 8]       = __float2half(oc[mt][dn][2] * inv1);
            sQ[(d0 + 1) * SQ_STRIDE + qc + g + 8] = __float2half(oc[mt][dn][3] * inv1);
        }
    }
    __syncthreads();
    __half* AO = g_AOh + base;
    #pragma unroll
    for (int i = 0; i < 8; i++) {
        int idx = tid + i * 256;
        int row = idx >> 6, cc = (idx & 63) << 3;
        *(uint4*)(AO + (size_t)row * Nn + q0 + cc) =
            *(uint4*)(sQ + row * SQ_STRIDE + cc);
    }
}

// ---------------------------------------------------------------------------
// Launch
// ---------------------------------------------------------------------------
extern "C" void kernel_launch(void* const* d_in, const int* in_sizes, int n_in,
                              void* d_out, int out_size) {
    const float* x    = (const float*)d_in[0];
    const float* gn_w = (const float*)d_in[1];
    const float* gn_b = (const float*)d_in[2];
    const float* wq   = (const float*)d_in[3];
    const float* bq   = (const float*)d_in[4];
    const float* wk   = (const float*)d_in[5];
    const float* bk   = (const float*)d_in[6];
    const float* wv   = (const float*)d_in[7];
    const float* bv   = (const float*)d_in[8];
    const float* wo   = (const float*)d_in[9];
    const float* bo   = (const float*)d_in[10];
    float* out = (float*)d_out;

    __half* wh;
    cudaGetSymbolAddress((void**)&wh, g_Wh);

    static bool attr_set = false;
    if (!attr_set) {
        cudaFuncSetAttribute(attn_kernel,
                             cudaFuncAttributeMaxDynamicSharedMemorySize,
                             ATTN_SMEM_BYTES);
        attr_set = true;
    }

    wconv_kernel<<<256, 256>>>(wq, wk, wv, wo);
    gn_part_kernel<<<128, 256>>>(x);
    gn_fin_kernel<<<1, 512>>>(gn_w, gn_b);
    normalize_kernel<<<(Bsz * Cc * Nn / 4) / 512, 256>>>(x);

    gemm_qkv<<<dim3(Nn / 128, 6, Bsz), 256>>>(wh, bq, bk, bv);

    attn_kernel<<<dim3(Nn / 512, Hh, Bsz), 256, ATTN_SMEM_BYTES>>>();

    gemm_o<<<dim3(Nn / 128, Cc / 128, Bsz), 256>>>(wh + 3 * Cc * Cc, bo, x, out);
}